// round 9
// baseline (speedup 1.0000x reference)
#include <cuda_runtime.h>
#include <cuda_fp16.h>
#include <math.h>
#include <float.h>

// ---------------------------------------------------------------------------
// Problem constants (fixed by the dataset)
// ---------------------------------------------------------------------------
#define NMAX 50048
#define EMAX 1600000
#define GMAXC 64

typedef unsigned long long ull;

// ---------------------------------------------------------------------------
// Scratch (static device globals; no allocation at runtime)
// ---------------------------------------------------------------------------
__device__ ull   g_degcnt[NMAX];
__device__ float g_dinv[NMAX];
__device__ int   g_cnt[NMAX];
__device__ int   g_fill[NMAX];
__device__ int   g_rowstart[NMAX];
__device__ int   g_total;
__device__ int2  g_epack[EMAX];
__device__ float g_T1[NMAX * 16];      // layer-0 C1 (fp32, pointwise reads only)
__device__ float g_H [NMAX * 256];     // fp32 activations (pre-BN)
__device__ __half g_Zh [NMAX * 128];
__device__ __half g_T1h[NMAX * 128];
__device__ __half g_T2h[NMAX * 128];
__device__ float g_bnsum[1024];        // [4 layers][256]
__device__ float g_bnsq [1024];
__device__ int   g_poolmax[GMAXC * 256];
__device__ float g_poolsum[GMAXC * 256];
__device__ int   g_segstart[GMAXC + 1];

// ---------------------------------------------------------------------------
// Helpers
// ---------------------------------------------------------------------------
__device__ __forceinline__ float softplus_f(float x) {
    return fmaxf(x, 0.f) + log1pf(expf(-fabsf(x)));
}

__device__ __forceinline__ int fmap_f(float f) {
    int i = __float_as_int(f);
    return (i < 0) ? (i ^ 0x7FFFFFFF) : i;
}
__device__ __forceinline__ float funmap_f(int k) {
    return __int_as_float((k < 0) ? (k ^ 0x7FFFFFFF) : k);
}

// packed fp32x2 FMA (Blackwell): d = a*b + d per 32-bit lane
__device__ __forceinline__ void fma2(ull &d, ull a, ull b) {
    asm("fma.rn.f32x2 %0, %1, %2, %0;" : "+l"(d) : "l"(a), "l"(b));
}
__device__ __forceinline__ ull bc2(float a) {
    ull r; unsigned int u = __float_as_uint(a);
    asm("mov.b64 %0, {%1, %1};" : "=l"(r) : "r"(u));
    return r;
}
union F2U { ull u; float2 f; };
union H2I { __half2 h; int i; };

// fp16 tensor-core mma: D(16x8,f32) += A(16x16,f16) * B(16x8,f16)
__device__ __forceinline__ void mma_f16(
    float &c0, float &c1, float &c2, float &c3,
    unsigned int a0, unsigned int a1, unsigned int a2, unsigned int a3,
    unsigned int b0, unsigned int b1)
{
    asm volatile(
        "mma.sync.aligned.m16n8k16.row.col.f32.f16.f16.f32 "
        "{%0,%1,%2,%3}, {%4,%5,%6,%7}, {%8,%9}, {%0,%1,%2,%3};"
        : "+f"(c0), "+f"(c1), "+f"(c2), "+f"(c3)
        : "r"(a0), "r"(a1), "r"(a2), "r"(a3), "r"(b0), "r"(b1));
}

// ---------------------------------------------------------------------------
// Preprocessing
// ---------------------------------------------------------------------------
__global__ void zero_init_k(int n) {
    int i = blockIdx.x * blockDim.x + threadIdx.x;
    if (i < n) { g_degcnt[i] = 0ull; g_fill[i] = 0; }
    if (i < 1024) { g_bnsum[i] = 0.f; g_bnsq[i] = 0.f; }
    if (i == 0) g_total = 0;
}

// one 64-bit atomic per edge: count in bits[40:], deg-sum as 24-bit fixed point
__global__ void edge_deg_k(const int* __restrict__ ei, const float* __restrict__ ew, int E) {
    int e = blockIdx.x * blockDim.x + threadIdx.x;
    if (e >= E) return;
    int r = ei[e];
    ull v = (1ull << 40) | (ull)__float2uint_rn(ew[e] * 16777216.f);
    atomicAdd(&g_degcnt[r], v);
}

// fused: unpack deg/cnt + dinv + per-block scan + one global atomic per block
__global__ void rowbase_k(int n) {
    __shared__ int wsum[32];
    __shared__ int blockbase;
    int tid = threadIdx.x, lane = tid & 31, wid = tid >> 5;
    int i = blockIdx.x * 1024 + tid;
    int v = 0;
    if (i < n) {
        ull dv = g_degcnt[i];
        v = (int)(dv >> 40);
        float d = (float)(dv & 0xFFFFFFFFFFull) * (1.f / 16777216.f);
        g_dinv[i] = (d > 0.f) ? rsqrtf(d) : 0.f;
        g_cnt[i] = v;
    }
    int x = v;
#pragma unroll
    for (int off = 1; off < 32; off <<= 1) {
        int t = __shfl_up_sync(0xffffffffu, x, off);
        if (lane >= off) x += t;
    }
    if (lane == 31) wsum[wid] = x;
    __syncthreads();
    if (wid == 0) {
        int y = wsum[lane];
#pragma unroll
        for (int off = 1; off < 32; off <<= 1) {
            int t = __shfl_up_sync(0xffffffffu, y, off);
            if (lane >= off) y += t;
        }
        wsum[lane] = y;
    }
    __syncthreads();
    if (tid == 0) blockbase = atomicAdd(&g_total, wsum[31]);
    __syncthreads();
    int pre = (wid > 0) ? wsum[wid - 1] : 0;
    if (i < n) g_rowstart[i] = blockbase + pre + x - v;
}

__global__ void edge_fill_k(const int* __restrict__ ei, const float* __restrict__ ew, int E) {
    int e = blockIdx.x * blockDim.x + threadIdx.x;
    if (e >= E) return;
    int r = ei[e];
    int c = ei[E + e];
    int p = g_rowstart[r] + atomicAdd(&g_fill[r], 1);
    float nw = -ew[e] * g_dinv[r] * g_dinv[c];
    g_epack[p] = make_int2(c, __float_as_int(nw));
}

// ---------------------------------------------------------------------------
// Sparse propagation (half state, fp32 accumulate). Thread = (row, 8 features).
// MODE 0: g_Zh  -> g_T1h            (generic T1 = L Z)
// MODE 1: g_T1h -> g_T2h            (generic T2raw = L T1)
// MODE 2: gather g_Zh (=C2), out g_T1h = half(g_T1_f32 + 2*acc)       [layer 0]
// MODE 3: gather g_T1h (=T), out g_H = sp(g_H - toF(g_Zh) + acc + b)
//         + fused BN stats for layer 0                                 [layer 0]
// ---------------------------------------------------------------------------
template<int MODE>
__global__ void prop_h_k(int n, int fi8, const float* __restrict__ bias) {
    __shared__ float ssum[16], ssq[16];
    int flat = threadIdx.y * blockDim.x + threadIdx.x;
    if (MODE == 3) {
        if (flat < 16) { ssum[flat] = 0.f; ssq[flat] = 0.f; }
        __syncthreads();
    }
    int row = blockIdx.x * blockDim.y + threadIdx.y;
    if (row >= n) return;
    const int4* Zin = (const int4*)((MODE == 0 || MODE == 2) ? g_Zh : g_T1h);
    int xf = threadIdx.x;
    int s = g_rowstart[row];
    int e = s + g_cnt[row];
    float acc[8];
#pragma unroll
    for (int j = 0; j < 8; j++) acc[j] = 0.f;
    int i = s;
    for (; i + 4 <= e; i += 4) {
        int2 e0 = g_epack[i], e1 = g_epack[i + 1], e2 = g_epack[i + 2], e3 = g_epack[i + 3];
        int4 v0 = Zin[e0.x * fi8 + xf];
        int4 v1 = Zin[e1.x * fi8 + xf];
        int4 v2 = Zin[e2.x * fi8 + xf];
        int4 v3 = Zin[e3.x * fi8 + xf];
        float w0 = __int_as_float(e0.y), w1 = __int_as_float(e1.y);
        float w2 = __int_as_float(e2.y), w3 = __int_as_float(e3.y);
        const __half2* h0 = (const __half2*)&v0;
        const __half2* h1 = (const __half2*)&v1;
        const __half2* h2 = (const __half2*)&v2;
        const __half2* h3 = (const __half2*)&v3;
#pragma unroll
        for (int j = 0; j < 4; j++) {
            float2 f0 = __half22float2(h0[j]);
            float2 f1 = __half22float2(h1[j]);
            float2 f2 = __half22float2(h2[j]);
            float2 f3 = __half22float2(h3[j]);
            acc[2*j]   = fmaf(w0, f0.x, acc[2*j]);   acc[2*j+1] = fmaf(w0, f0.y, acc[2*j+1]);
            acc[2*j]   = fmaf(w1, f1.x, acc[2*j]);   acc[2*j+1] = fmaf(w1, f1.y, acc[2*j+1]);
            acc[2*j]   = fmaf(w2, f2.x, acc[2*j]);   acc[2*j+1] = fmaf(w2, f2.y, acc[2*j+1]);
            acc[2*j]   = fmaf(w3, f3.x, acc[2*j]);   acc[2*j+1] = fmaf(w3, f3.y, acc[2*j+1]);
        }
    }
    for (; i < e; i++) {
        int2 e0 = g_epack[i];
        int4 v0 = Zin[e0.x * fi8 + xf];
        float w0 = __int_as_float(e0.y);
        const __half2* h0 = (const __half2*)&v0;
#pragma unroll
        for (int j = 0; j < 4; j++) {
            float2 f0 = __half22float2(h0[j]);
            acc[2*j]   = fmaf(w0, f0.x, acc[2*j]);
            acc[2*j+1] = fmaf(w0, f0.y, acc[2*j+1]);
        }
    }
    int idx = row * fi8 + xf;
    if (MODE == 0 || MODE == 1) {
        int4 o; __half2* op = (__half2*)&o;
#pragma unroll
        for (int j = 0; j < 4; j++) op[j] = __floats2half2_rn(acc[2*j], acc[2*j+1]);
        ((int4*)(MODE == 0 ? g_T1h : g_T2h))[idx] = o;
    } else if (MODE == 2) {
        // T = C1 + 2 * acc   (C1 fp32 pointwise)
        int fbase = row * (fi8 * 2) + xf * 2;
        float4 c1a = ((const float4*)g_T1)[fbase];
        float4 c1b = ((const float4*)g_T1)[fbase + 1];
        float cv[8] = {c1a.x, c1a.y, c1a.z, c1a.w, c1b.x, c1b.y, c1b.z, c1b.w};
        int4 o; __half2* op = (__half2*)&o;
#pragma unroll
        for (int j = 0; j < 4; j++)
            op[j] = __floats2half2_rn(cv[2*j] + 2.f*acc[2*j], cv[2*j+1] + 2.f*acc[2*j+1]);
        ((int4*)g_T1h)[idx] = o;
    } else {
        // H = softplus(C0 - C2 + acc + b), fused layer-0 BN stats
        int fbase = row * (fi8 * 2) + xf * 2;
        float4 h0 = ((const float4*)g_H)[fbase];
        float4 h1 = ((const float4*)g_H)[fbase + 1];
        float hv[8] = {h0.x, h0.y, h0.z, h0.w, h1.x, h1.y, h1.z, h1.w};
        int4 vz = ((const int4*)g_Zh)[idx];
        const __half2* hz = (const __half2*)&vz;
        float4 b0 = ((const float4*)bias)[xf * 2];
        float4 b1 = ((const float4*)bias)[xf * 2 + 1];
        float bv[8] = {b0.x, b0.y, b0.z, b0.w, b1.x, b1.y, b1.z, b1.w};
        float ov[8];
#pragma unroll
        for (int j = 0; j < 4; j++) {
            float2 fz = __half22float2(hz[j]);
            ov[2*j]   = softplus_f(hv[2*j]   - fz.x + acc[2*j]   + bv[2*j]);
            ov[2*j+1] = softplus_f(hv[2*j+1] - fz.y + acc[2*j+1] + bv[2*j+1]);
        }
        ((float4*)g_H)[fbase]     = make_float4(ov[0], ov[1], ov[2], ov[3]);
        ((float4*)g_H)[fbase + 1] = make_float4(ov[4], ov[5], ov[6], ov[7]);
#pragma unroll
        for (int j = 0; j < 8; j++) {
            atomicAdd(&ssum[xf * 8 + j], ov[j]);
            atomicAdd(&ssq [xf * 8 + j], ov[j] * ov[j]);
        }
        __syncthreads();
        if (flat < 16) {
            atomicAdd(&g_bnsum[flat], ssum[flat]);
            atomicAdd(&g_bnsq [flat], ssq[flat]);
        }
    }
}

// ---------------------------------------------------------------------------
// Layer-0 commuted GEMM: C0 = x@W0 -> g_H (fp32), C1 = x@W1 -> g_T1 (fp32),
// C2 = x@W2 -> g_Zh (half).  FI=128, per-mat FO=16.
// ---------------------------------------------------------------------------
__global__ void __launch_bounds__(128) cheb_gemm0_k(
    const float* __restrict__ x, const float* __restrict__ W, int n)
{
    constexpr int CG = 4, RPI = 32, RM = 4, BM = RPI * RM;   // BM = 128
    const int cg = threadIdx.x % CG, r0 = threadIdx.x / CG;
    const int rowbase = blockIdx.x * BM;
    const ulonglong2* Wp = (const ulonglong2*)W;   // [3][128][4] of ull2
    const float4* X4 = (const float4*)x;

    ull acc0[RM][2], acc1[RM][2], acc2[RM][2];
    int rows[RM]; bool vld[RM];
#pragma unroll
    for (int r = 0; r < RM; r++) {
        acc0[r][0] = acc0[r][1] = 0ull;
        acc1[r][0] = acc1[r][1] = 0ull;
        acc2[r][0] = acc2[r][1] = 0ull;
        rows[r] = rowbase + r0 + r * RPI;
        vld[r]  = rows[r] < n;
    }

    for (int k0 = 0; k0 < 128; k0 += 4) {
        ulonglong2 w0[4], w1[4], w2[4];
#pragma unroll
        for (int kk = 0; kk < 4; kk++) {
            int wi = (k0 + kk) * CG + cg;
            w0[kk] = Wp[wi];
            w1[kk] = Wp[512 + wi];
            w2[kk] = Wp[1024 + wi];
        }
#pragma unroll
        for (int r = 0; r < RM; r++) {
            float4 z4 = make_float4(0.f, 0.f, 0.f, 0.f);
            if (vld[r]) z4 = X4[rows[r] * 32 + (k0 >> 2)];
            float zz[4] = {z4.x, z4.y, z4.z, z4.w};
#pragma unroll
            for (int kk = 0; kk < 4; kk++) {
                ull a2 = bc2(zz[kk]);
                fma2(acc0[r][0], a2, w0[kk].x); fma2(acc0[r][1], a2, w0[kk].y);
                fma2(acc1[r][0], a2, w1[kk].x); fma2(acc1[r][1], a2, w1[kk].y);
                fma2(acc2[r][0], a2, w2[kk].x); fma2(acc2[r][1], a2, w2[kk].y);
            }
        }
    }

#pragma unroll
    for (int r = 0; r < RM; r++) {
        if (!vld[r]) continue;
        int off = rows[r] * CG + cg;
        F2U l, h;
        l.u = acc0[r][0]; h.u = acc0[r][1];
        ((float4*)g_H )[off] = make_float4(l.f.x, l.f.y, h.f.x, h.f.y);
        l.u = acc1[r][0]; h.u = acc1[r][1];
        ((float4*)g_T1)[off] = make_float4(l.f.x, l.f.y, h.f.x, h.f.y);
        l.u = acc2[r][0]; h.u = acc2[r][1];
        H2I p0, p1;
        p0.h = __floats2half2_rn(l.f.x, l.f.y);
        p1.h = __floats2half2_rn(h.f.x, h.f.y);
        ((int2*)g_Zh)[off] = make_int2(p0.i, p1.i);
    }
}

// ---------------------------------------------------------------------------
// SIMT Chebyshev combine GEMM (layers 1-2), f32x2 packed, half inputs,
// fused BN stats:  H = Z W0 + T1 W1 + (2 T2raw - Z) W2 + b  (+ softplus)
// ---------------------------------------------------------------------------
template<int FI, int FO, int RM, int THREADS, bool ACT>
__global__ void __launch_bounds__(THREADS) cheb_gemm2_k(
    const float* __restrict__ W, const float* __restrict__ b, int n, int lidx)
{
    constexpr int CG = FO / 4;
    constexpr int RPI = THREADS / CG;
    constexpr int BM = RPI * RM;
    __shared__ float ssum[FO], ssq[FO];
    const int tid = threadIdx.x;
    const int cg = tid % CG, r0 = tid / CG;
    const int rowbase = blockIdx.x * BM;
    if (tid < FO) { ssum[tid] = 0.f; ssq[tid] = 0.f; }
    __syncthreads();

    const ulonglong2* Wp = (const ulonglong2*)W;   // [3][FI][CG] of ull2
    const int2* Zh = (const int2*)g_Zh;
    const int2* Ah = (const int2*)g_T1h;
    const int2* Ph = (const int2*)g_T2h;

    ulonglong2 bb = ((const ulonglong2*)b)[cg];
    ull acc[RM][2];
    int rows[RM]; bool vld[RM];
#pragma unroll
    for (int r = 0; r < RM; r++) {
        acc[r][0] = bb.x; acc[r][1] = bb.y;
        rows[r] = rowbase + r0 + r * RPI;
        vld[r]  = rows[r] < n;
    }

    for (int k0 = 0; k0 < FI; k0 += 4) {
        ulonglong2 w0[4], w1[4], w2[4];
#pragma unroll
        for (int kk = 0; kk < 4; kk++) {
            int wi = (k0 + kk) * CG + cg;
            w0[kk] = Wp[wi];
            w1[kk] = Wp[FI * CG + wi];
            w2[kk] = Wp[2 * FI * CG + wi];
        }
#pragma unroll
        for (int r = 0; r < RM; r++) {
            float zz[4] = {0.f, 0.f, 0.f, 0.f};
            float tt[4] = {0.f, 0.f, 0.f, 0.f};
            float uu[4] = {0.f, 0.f, 0.f, 0.f};
            if (vld[r]) {
                int off = rows[r] * (FI / 4) + (k0 >> 2);
                int2 vz = Zh[off], va = Ah[off], vp = Ph[off];
                H2I u;
                u.i = vz.x; float2 z0 = __half22float2(u.h);
                u.i = vz.y; float2 z1 = __half22float2(u.h);
                u.i = va.x; float2 a0 = __half22float2(u.h);
                u.i = va.y; float2 a1 = __half22float2(u.h);
                u.i = vp.x; float2 p0 = __half22float2(u.h);
                u.i = vp.y; float2 p1 = __half22float2(u.h);
                zz[0] = z0.x; zz[1] = z0.y; zz[2] = z1.x; zz[3] = z1.y;
                tt[0] = a0.x; tt[1] = a0.y; tt[2] = a1.x; tt[3] = a1.y;
                uu[0] = 2.f*p0.x - z0.x; uu[1] = 2.f*p0.y - z0.y;
                uu[2] = 2.f*p1.x - z1.x; uu[3] = 2.f*p1.y - z1.y;
            }
#pragma unroll
            for (int kk = 0; kk < 4; kk++) {
                ull a2 = bc2(zz[kk]);
                fma2(acc[r][0], a2, w0[kk].x); fma2(acc[r][1], a2, w0[kk].y);
                ull t2 = bc2(tt[kk]);
                fma2(acc[r][0], t2, w1[kk].x); fma2(acc[r][1], t2, w1[kk].y);
                ull u2 = bc2(uu[kk]);
                fma2(acc[r][0], u2, w2[kk].x); fma2(acc[r][1], u2, w2[kk].y);
            }
        }
    }

    float ls[4] = {0.f, 0.f, 0.f, 0.f}, lq[4] = {0.f, 0.f, 0.f, 0.f};
#pragma unroll
    for (int r = 0; r < RM; r++) {
        if (!vld[r]) continue;
        F2U l, h; l.u = acc[r][0]; h.u = acc[r][1];
        float4 o = make_float4(l.f.x, l.f.y, h.f.x, h.f.y);
        if (ACT) {
            o.x = softplus_f(o.x); o.y = softplus_f(o.y);
            o.z = softplus_f(o.z); o.w = softplus_f(o.w);
        }
        ((float4*)g_H)[rows[r] * CG + cg] = o;
        ls[0] += o.x; ls[1] += o.y; ls[2] += o.z; ls[3] += o.w;
        lq[0] = fmaf(o.x, o.x, lq[0]); lq[1] = fmaf(o.y, o.y, lq[1]);
        lq[2] = fmaf(o.z, o.z, lq[2]); lq[3] = fmaf(o.w, o.w, lq[3]);
    }
#pragma unroll
    for (int j = 0; j < 4; j++) {
        atomicAdd(&ssum[cg * 4 + j], ls[j]);
        atomicAdd(&ssq [cg * 4 + j], lq[j]);
    }
    __syncthreads();
    if (tid < FO) {
        atomicAdd(&g_bnsum[lidx * 256 + tid], ssum[tid]);
        atomicAdd(&g_bnsq [lidx * 256 + tid], ssq[tid]);
    }
}

// ---------------------------------------------------------------------------
// fp16 tensor-core Chebyshev combine GEMM, layers 3-4 (m16n8k16).
// A (half) from g_Zh/g_T1h/g_T2h (seg2 = 2*T2 - Z in half2).
// B (fp32 weights) converted to half into a transposed smem tile.
// Block tile 128x64, 8 warps (4x2), KC=32. ACT fuses BN stats.
// ---------------------------------------------------------------------------
template<int FI, int FO, bool ACT>
__global__ void __launch_bounds__(256) cheb_mma_k(
    const float* __restrict__ W, const float* __restrict__ bias, int n, int lidx)
{
    constexpr int BM = 128, BN = 64, KC = 32;
    constexpr int APAD = 56;   // halves per As row (112B, 16B-aligned, conflict-free)
    constexpr int BPAD = 40;   // halves per Bst row
    __shared__ __half As[BM][APAD];
    __shared__ __half Bst[BN][BPAD];   // transposed: [n][k]
    __shared__ float ssum[BN], ssq[BN];

    const int tid  = threadIdx.x;
    const int lane = tid & 31, wid = tid >> 5;
    const int wm = wid & 3, wn = wid >> 2;
    const int g = lane >> 2, tig = lane & 3;
    const int row0 = blockIdx.x * BM;
    const int n0   = blockIdx.y * BN;

    if (ACT) {
        if (tid < BN) { ssum[tid] = 0.f; ssq[tid] = 0.f; }
    }

    float c[2][4][4];
#pragma unroll
    for (int mt = 0; mt < 2; mt++)
#pragma unroll
        for (int nt = 0; nt < 4; nt++)
#pragma unroll
            for (int j = 0; j < 4; j++) c[mt][nt][j] = 0.f;

    // A loader: thread -> row (tid & 127), 16-half chunk at (tid>>7)*16
    const int lrow = tid & 127;
    const int lcol = (tid >> 7) * 16;
    const int grow = row0 + lrow;
    const bool lvalid = grow < n;
    // B loader: thread -> k = tid>>3 (0..31), 8 cols at (tid&7)*8
    const int bk = tid >> 3;
    const int bn = (tid & 7) * 8;

    for (int seg = 0; seg < 3; seg++) {
        const float* Wseg = W + seg * FI * FO;
        for (int kb = 0; kb < FI; kb += KC) {
            // ---- A tile: two int4 (16 halves) per thread, no conversion ----
            int4 va = make_int4(0, 0, 0, 0), vb = va;
            if (lvalid) {
                int base = (grow * FI + kb + lcol) >> 3;   // int4 index
                if (seg == 0) {
                    va = ((const int4*)g_Zh)[base];
                    vb = ((const int4*)g_Zh)[base + 1];
                } else if (seg == 1) {
                    va = ((const int4*)g_T1h)[base];
                    vb = ((const int4*)g_T1h)[base + 1];
                } else {
                    int4 p0 = ((const int4*)g_T2h)[base];
                    int4 p1 = ((const int4*)g_T2h)[base + 1];
                    int4 z0 = ((const int4*)g_Zh)[base];
                    int4 z1 = ((const int4*)g_Zh)[base + 1];
                    __half2* pa = (__half2*)&va; __half2* pb = (__half2*)&vb;
                    const __half2* pp0 = (const __half2*)&p0;
                    const __half2* pp1 = (const __half2*)&p1;
                    const __half2* pz0 = (const __half2*)&z0;
                    const __half2* pz1 = (const __half2*)&z1;
#pragma unroll
                    for (int j = 0; j < 4; j++) {
                        pa[j] = __hsub2(__hadd2(pp0[j], pp0[j]), pz0[j]);
                        pb[j] = __hsub2(__hadd2(pp1[j], pp1[j]), pz1[j]);
                    }
                }
            }
            *(int4*)&As[lrow][lcol]     = va;
            *(int4*)&As[lrow][lcol + 8] = vb;
            // ---- B tile: 8 fp32 -> 8 half, transposed store ----
            {
                const float* wrow = Wseg + (kb + bk) * FO + n0 + bn;
                float4 w0 = *(const float4*)wrow;
                float4 w1 = *(const float4*)(wrow + 4);
                Bst[bn + 0][bk] = __float2half_rn(w0.x);
                Bst[bn + 1][bk] = __float2half_rn(w0.y);
                Bst[bn + 2][bk] = __float2half_rn(w0.z);
                Bst[bn + 3][bk] = __float2half_rn(w0.w);
                Bst[bn + 4][bk] = __float2half_rn(w1.x);
                Bst[bn + 5][bk] = __float2half_rn(w1.y);
                Bst[bn + 6][bk] = __float2half_rn(w1.z);
                Bst[bn + 7][bk] = __float2half_rn(w1.w);
            }
            __syncthreads();
            // ---- compute: 2 k16 steps ----
#pragma unroll
            for (int k16 = 0; k16 < KC; k16 += 16) {
                unsigned int af[2][4];
#pragma unroll
                for (int mt = 0; mt < 2; mt++) {
                    int r = wm * 32 + mt * 16 + g;
                    af[mt][0] = *(const unsigned int*)&As[r    ][k16 + 2 * tig];
                    af[mt][1] = *(const unsigned int*)&As[r + 8][k16 + 2 * tig];
                    af[mt][2] = *(const unsigned int*)&As[r    ][k16 + 2 * tig + 8];
                    af[mt][3] = *(const unsigned int*)&As[r + 8][k16 + 2 * tig + 8];
                }
                unsigned int bf[4][2];
#pragma unroll
                for (int nt = 0; nt < 4; nt++) {
                    int cc = wn * 32 + nt * 8 + g;
                    bf[nt][0] = *(const unsigned int*)&Bst[cc][k16 + 2 * tig];
                    bf[nt][1] = *(const unsigned int*)&Bst[cc][k16 + 2 * tig + 8];
                }
#pragma unroll
                for (int mt = 0; mt < 2; mt++)
#pragma unroll
                    for (int nt = 0; nt < 4; nt++)
                        mma_f16(c[mt][nt][0], c[mt][nt][1], c[mt][nt][2], c[mt][nt][3],
                                af[mt][0], af[mt][1], af[mt][2], af[mt][3],
                                bf[nt][0], bf[nt][1]);
            }
            __syncthreads();
        }
    }

    float ls[4][2], lq[4][2];
    if (ACT) {
#pragma unroll
        for (int nt = 0; nt < 4; nt++) {
            ls[nt][0] = ls[nt][1] = 0.f;
            lq[nt][0] = lq[nt][1] = 0.f;
        }
    }
#pragma unroll
    for (int mt = 0; mt < 2; mt++) {
        int r_lo = row0 + wm * 32 + mt * 16 + g;
        int r_hi = r_lo + 8;
#pragma unroll
        for (int nt = 0; nt < 4; nt++) {
            int col = n0 + wn * 32 + nt * 8 + 2 * tig;
            float b0 = bias[col], b1 = bias[col + 1];
            float o0 = c[mt][nt][0] + b0, o1 = c[mt][nt][1] + b1;
            float o2 = c[mt][nt][2] + b0, o3 = c[mt][nt][3] + b1;
            if (ACT) {
                o0 = softplus_f(o0); o1 = softplus_f(o1);
                o2 = softplus_f(o2); o3 = softplus_f(o3);
            }
            if (r_lo < n) {
                *(float2*)&g_H[r_lo * FO + col] = make_float2(o0, o1);
                if (ACT) {
                    ls[nt][0] += o0; ls[nt][1] += o1;
                    lq[nt][0] = fmaf(o0, o0, lq[nt][0]);
                    lq[nt][1] = fmaf(o1, o1, lq[nt][1]);
                }
            }
            if (r_hi < n) {
                *(float2*)&g_H[r_hi * FO + col] = make_float2(o2, o3);
                if (ACT) {
                    ls[nt][0] += o2; ls[nt][1] += o3;
                    lq[nt][0] = fmaf(o2, o2, lq[nt][0]);
                    lq[nt][1] = fmaf(o3, o3, lq[nt][1]);
                }
            }
        }
    }
    if (ACT) {
        __syncthreads();
#pragma unroll
        for (int nt = 0; nt < 4; nt++) {
            int lc = wn * 32 + nt * 8 + 2 * tig;
            atomicAdd(&ssum[lc],     ls[nt][0]);
            atomicAdd(&ssum[lc + 1], ls[nt][1]);
            atomicAdd(&ssq [lc],     lq[nt][0]);
            atomicAdd(&ssq [lc + 1], lq[nt][1]);
        }
        __syncthreads();
        if (tid < BN) {
            atomicAdd(&g_bnsum[lidx * 256 + n0 + tid], ssum[tid]);
            atomicAdd(&g_bnsq [lidx * 256 + n0 + tid], ssq[tid]);
        }
    }
}

// ---------------------------------------------------------------------------
// BN finalize+apply (stats already accumulated by producer kernels)
// ---------------------------------------------------------------------------
__global__ void bn_apply_h_k(int total4, int fo,
                             const float* __restrict__ gma,
                             const float* __restrict__ beta, int l, int n) {
    __shared__ float s_sc[256], s_sh[256];
    int tid = threadIdx.x;
    if (tid < fo) {
        float inv_n = 1.f / (float)n;
        float m = g_bnsum[l * 256 + tid] * inv_n;
        float v = g_bnsq[l * 256 + tid] * inv_n - m * m;
        float sc = gma[tid] * rsqrtf(fmaxf(v, 0.f) + 1e-5f);
        s_sc[tid] = sc;
        s_sh[tid] = beta[tid] - m * sc;
    }
    __syncthreads();
    int fo4 = fo >> 2;
    for (int i = blockIdx.x * blockDim.x + tid; i < total4;
         i += gridDim.x * blockDim.x) {
        float4 h = ((const float4*)g_H)[i];
        int f = (i % fo4) * 4;
        H2I a, b;
        a.h = __floats2half2_rn(fmaf(h.x, s_sc[f],     s_sh[f]),
                                fmaf(h.y, s_sc[f + 1], s_sh[f + 1]));
        b.h = __floats2half2_rn(fmaf(h.z, s_sc[f + 2], s_sh[f + 2]),
                                fmaf(h.w, s_sc[f + 3], s_sh[f + 3]));
        ((int2*)g_Zh)[i] = make_int2(a.i, b.i);
    }
}

// ---------------------------------------------------------------------------
// Pooling + dense head
// ---------------------------------------------------------------------------
__global__ void pool_setup_k(const int* __restrict__ batch, int n, int G) {
    int i = blockIdx.x * blockDim.x + threadIdx.x;
    if (i < G * 256) { g_poolmax[i] = INT_MIN; g_poolsum[i] = 0.f; }
    if (i <= G) {
        if (i == G) { g_segstart[G] = n; }
        else {
            int lo = 0, hi = n;
            while (lo < hi) {
                int mid = (lo + hi) >> 1;
                if (batch[mid] < i) lo = mid + 1; else hi = mid;
            }
            g_segstart[i] = lo;
        }
    }
}

#define POOL_ROWS 128
__global__ void pool_k(const int* __restrict__ batch, int n) {
    int f  = threadIdx.x;               // 256 features
    int rs = blockIdx.x * POOL_ROWS;
    if (rs >= n) return;
    int re = min(rs + POOL_ROWS, n);
    int cur = batch[rs];
    float mx = -FLT_MAX, sm = 0.f;
    for (int r = rs; r < re; r++) {
        int g = batch[r];
        if (g != cur) {
            atomicMax(&g_poolmax[cur * 256 + f], fmap_f(mx));
            atomicAdd(&g_poolsum[cur * 256 + f], sm);
            cur = g; mx = -FLT_MAX; sm = 0.f;
        }
        float v = g_H[r * 256 + f];
        mx = fmaxf(mx, v); sm += v;
    }
    atomicMax(&g_poolmax[cur * 256 + f], fmap_f(mx));
    atomicAdd(&g_poolsum[cur * 256 + f], sm);
}

__global__ void dense_k(const float* __restrict__ Wd, const float* __restrict__ bd,
                        float* __restrict__ out) {
    __shared__ float sh[4][128];
    int g = blockIdx.x, tid = threadIdx.x;
    int s = g_segstart[g], e = g_segstart[g + 1];
    float cnt = fmaxf((float)(e - s), 1.f);
    float a[4] = {0.f, 0.f, 0.f, 0.f};
    for (int k = tid; k < 512; k += 128) {
        float pv;
        if (k < 256) {
            int key = g_poolmax[g * 256 + k];
            pv = (key == INT_MIN) ? 0.f : funmap_f(key);
        } else {
            pv = g_poolsum[g * 256 + (k - 256)] / cnt;
        }
#pragma unroll
        for (int j = 0; j < 4; j++) a[j] = fmaf(pv, Wd[k * 4 + j], a[j]);
    }
#pragma unroll
    for (int j = 0; j < 4; j++) sh[j][tid] = a[j];
    __syncthreads();
    for (int off = 64; off >= 1; off >>= 1) {
        if (tid < off) {
#pragma unroll
            for (int j = 0; j < 4; j++) sh[j][tid] += sh[j][tid + off];
        }
        __syncthreads();
    }
    if (tid == 0) {
        float l[4];
#pragma unroll
        for (int j = 0; j < 4; j++) l[j] = sh[j][0] + bd[j];
        float m = fmaxf(fmaxf(l[0], l[1]), fmaxf(l[2], l[3]));
        float se = 0.f;
#pragma unroll
        for (int j = 0; j < 4; j++) se += expf(l[j] - m);
        float lse = m + logf(se);
#pragma unroll
        for (int j = 0; j < 4; j++) out[g * 4 + j] = l[j] - lse;
    }
}

// ---------------------------------------------------------------------------
// Host launcher
// ---------------------------------------------------------------------------
extern "C" void kernel_launch(void* const* d_in, const int* in_sizes, int n_in,
                              void* d_out, int out_size) {
    const float *x, *ew, *W[5], *b[5], *gm[4], *be[4], *Wd, *bd;
    const int *ei, *bi;

    bool setup_order = (in_sizes[2] > 1000000);
    if (setup_order) {
        x  = (const float*)d_in[0];
        ew = (const float*)d_in[1];
        ei = (const int*)  d_in[2];
        bi = (const int*)  d_in[3];
        int p = 4;
        for (int l = 0; l < 5; l++) {
            W[l] = (const float*)d_in[p++];
            b[l] = (const float*)d_in[p++];
            if (l < 4) { gm[l] = (const float*)d_in[p++]; be[l] = (const float*)d_in[p++]; }
        }
        Wd = (const float*)d_in[p++];
        bd = (const float*)d_in[p++];
    } else {
        x  = (const float*)d_in[0];
        ew = (const float*)d_in[1];
        int p = 2;
        for (int l = 0; l < 5; l++) {
            W[l] = (const float*)d_in[p++];
            b[l] = (const float*)d_in[p++];
            if (l < 4) { gm[l] = (const float*)d_in[p++]; be[l] = (const float*)d_in[p++]; }
        }
        Wd = (const float*)d_in[p++];
        bd = (const float*)d_in[p++];
        ei = (const int*)d_in[p++];
        bi = (const int*)d_in[p++];
    }

    const int n = in_sizes[0] / 128;
    const int E = in_sizes[1];
    const int G = out_size / 4;     // 64
    float* out = (float*)d_out;

    // side stream (created once; graph-capture forks/joins via events)
    static cudaStream_t s2 = nullptr;
    static cudaEvent_t evFork = nullptr, evJoin = nullptr;
    if (!s2) {
        cudaStreamCreateWithFlags(&s2, cudaStreamNonBlocking);
        cudaEventCreateWithFlags(&evFork, cudaEventDisableTiming);
        cudaEventCreateWithFlags(&evJoin, cudaEventDisableTiming);
    }

    // fork: layer-0 GEMM + pool setup run parallel to the CSR build
    cudaEventRecord(evFork, 0);
    cudaStreamWaitEvent(s2, evFork, 0);
    cheb_gemm0_k<<<(n + 127) / 128, 128, 0, s2>>>(x, W[0], n);
    pool_setup_k<<<(G * 256 + 255) / 256, 256, 0, s2>>>(bi, n, G);

    // main stream: packed deg/cnt, dinv, CSR build
    zero_init_k<<<(n + 255) / 256, 256>>>(n);
    edge_deg_k<<<(E + 255) / 256, 256>>>(ei, ew, E);
    rowbase_k<<<(n + 1023) / 1024, 1024>>>(n);
    edge_fill_k<<<(E + 255) / 256, 256>>>(ei, ew, E);

    // join
    cudaEventRecord(evJoin, s2);
    cudaStreamWaitEvent(0, evJoin, 0);

    // ---- Layer 0 (commuted; props at width 16, half state; stats fused) ----
    {
        dim3 blk(2, 128);
        int grd = (n + 127) / 128;
        prop_h_k<2><<<grd, blk>>>(n, 2, nullptr);   // T = C1 + 2 L C2  -> g_T1h
        prop_h_k<3><<<grd, blk>>>(n, 2, b[0]);      // H = sp(C0 - C2 + L T + b) + stats
    }
    {
        int total4 = n * 16 / 4;
        int agrid = (total4 + 255) / 256; if (agrid > 2048) agrid = 2048;
        bn_apply_h_k<<<agrid, 256>>>(total4, 16, gm[0], be[0], 0, n);
    }

    // ---- Layers 1-4 (all props on half state; stats fused in producers) ----
    for (int l = 1; l < 5; l++) {
        int gx = (n + 127) / 128;
        int fi8 = (l == 1) ? 2 : (l == 2) ? 4 : (l == 3) ? 8 : 16;
        dim3 blk(fi8, 256 / fi8);
        int grd = (n + blk.y - 1) / blk.y;
        prop_h_k<0><<<grd, blk>>>(n, fi8, nullptr);   // T1h = L Zh
        prop_h_k<1><<<grd, blk>>>(n, fi8, nullptr);   // T2h = L T1h

        switch (l) {
            case 1: cheb_gemm2_k< 16,  32, 4, 128, true ><<<(n + 63) / 64, 128>>>(W[1], b[1], n, 1); break;
            case 2: cheb_gemm2_k< 32,  64, 8, 128, true ><<<(n + 63) / 64, 128>>>(W[2], b[2], n, 2); break;
            case 3: cheb_mma_k< 64, 128, true ><<<dim3(gx, 2), 256>>>(W[3], b[3], n, 3); break;
            case 4: cheb_mma_k<128, 256, false><<<dim3(gx, 4), 256>>>(W[4], b[4], n, 4); break;
        }

        if (l < 4) {
            const int FO = (l == 1) ? 32 : (l == 2) ? 64 : 128;
            int total4 = n * FO / 4;
            int agrid = (total4 + 255) / 256; if (agrid > 2048) agrid = 2048;
            bn_apply_h_k<<<agrid, 256>>>(total4, FO, gm[l], be[l], l, n);
        }
    }

    // ---- pooling + dense head ----
    pool_k<<<(n + POOL_ROWS - 1) / POOL_ROWS, 256>>>(bi, n);
    dense_k<<<G, 128>>>(Wd, bd, out);
}

// round 10
// speedup vs baseline: 1.0502x; 1.0502x over previous
#include <cuda_runtime.h>
#include <cuda_fp16.h>
#include <math.h>
#include <float.h>

// ---------------------------------------------------------------------------
// Problem constants (fixed by the dataset)
// ---------------------------------------------------------------------------
#define NMAX 50048
#define EMAX 1600000
#define GMAXC 64

typedef unsigned long long ull;

// ---------------------------------------------------------------------------
// Scratch (static device globals; no allocation at runtime)
// ---------------------------------------------------------------------------
__device__ ull   g_degcnt[NMAX];
__device__ float g_dinv[NMAX];
__device__ int   g_cnt[NMAX];
__device__ int   g_fill[NMAX];
__device__ int   g_rowstart[NMAX];
__device__ int   g_total;
__device__ int2  g_epack[EMAX];
__device__ float g_T1[NMAX * 16];      // layer-0 C1 (fp32, pointwise reads only)
__device__ float g_H [NMAX * 256];     // fp32 activations (pre-BN)
__device__ __half g_Zh [NMAX * 128];
__device__ __half g_T1h[NMAX * 128];
__device__ __half g_T2h[NMAX * 128];
__device__ float g_bnsum[1024];        // [4 layers][256]
__device__ float g_bnsq [1024];
__device__ int   g_poolmax[GMAXC * 256];
__device__ float g_poolsum[GMAXC * 256];
__device__ int   g_segstart[GMAXC + 1];

// ---------------------------------------------------------------------------
// Helpers
// ---------------------------------------------------------------------------
__device__ __forceinline__ float softplus_f(float x) {
    return fmaxf(x, 0.f) + log1pf(expf(-fabsf(x)));
}

__device__ __forceinline__ int fmap_f(float f) {
    int i = __float_as_int(f);
    return (i < 0) ? (i ^ 0x7FFFFFFF) : i;
}
__device__ __forceinline__ float funmap_f(int k) {
    return __int_as_float((k < 0) ? (k ^ 0x7FFFFFFF) : k);
}

// packed fp32x2 FMA (Blackwell): d = a*b + d per 32-bit lane
__device__ __forceinline__ void fma2(ull &d, ull a, ull b) {
    asm("fma.rn.f32x2 %0, %1, %2, %0;" : "+l"(d) : "l"(a), "l"(b));
}
__device__ __forceinline__ ull bc2(float a) {
    ull r; unsigned int u = __float_as_uint(a);
    asm("mov.b64 %0, {%1, %1};" : "=l"(r) : "r"(u));
    return r;
}
union F2U { ull u; float2 f; };
union H2I { __half2 h; int i; };

__device__ __forceinline__ unsigned int tf32_of(float x) {
    unsigned int u;
    asm("cvt.rna.tf32.f32 %0, %1;" : "=r"(u) : "f"(x));
    return u;
}

__device__ __forceinline__ void mma_tf32(
    float &c0, float &c1, float &c2, float &c3,
    unsigned int a0, unsigned int a1, unsigned int a2, unsigned int a3,
    unsigned int b0, unsigned int b1)
{
    asm volatile(
        "mma.sync.aligned.m16n8k8.row.col.f32.tf32.tf32.f32 "
        "{%0,%1,%2,%3}, {%4,%5,%6,%7}, {%8,%9}, {%0,%1,%2,%3};"
        : "+f"(c0), "+f"(c1), "+f"(c2), "+f"(c3)
        : "r"(a0), "r"(a1), "r"(a2), "r"(a3), "r"(b0), "r"(b1));
}

// ---------------------------------------------------------------------------
// Preprocessing
// ---------------------------------------------------------------------------
__global__ void zero_init_k(int n) {
    int i = blockIdx.x * blockDim.x + threadIdx.x;
    if (i < n) { g_degcnt[i] = 0ull; g_fill[i] = 0; }
    if (i < 1024) { g_bnsum[i] = 0.f; g_bnsq[i] = 0.f; }
    if (i == 0) g_total = 0;
}

// one 64-bit atomic per edge: count in bits[40:], deg-sum as 24-bit fixed point
__global__ void edge_deg_k(const int* __restrict__ ei, const float* __restrict__ ew, int E) {
    int e = blockIdx.x * blockDim.x + threadIdx.x;
    if (e >= E) return;
    int r = ei[e];
    ull v = (1ull << 40) | (ull)__float2uint_rn(ew[e] * 16777216.f);
    atomicAdd(&g_degcnt[r], v);
}

// fused: unpack deg/cnt + dinv + per-block scan + one global atomic per block
__global__ void rowbase_k(int n) {
    __shared__ int wsum[32];
    __shared__ int blockbase;
    int tid = threadIdx.x, lane = tid & 31, wid = tid >> 5;
    int i = blockIdx.x * 1024 + tid;
    int v = 0;
    if (i < n) {
        ull dv = g_degcnt[i];
        v = (int)(dv >> 40);
        float d = (float)(dv & 0xFFFFFFFFFFull) * (1.f / 16777216.f);
        g_dinv[i] = (d > 0.f) ? rsqrtf(d) : 0.f;
        g_cnt[i] = v;
    }
    int x = v;
#pragma unroll
    for (int off = 1; off < 32; off <<= 1) {
        int t = __shfl_up_sync(0xffffffffu, x, off);
        if (lane >= off) x += t;
    }
    if (lane == 31) wsum[wid] = x;
    __syncthreads();
    if (wid == 0) {
        int y = wsum[lane];
#pragma unroll
        for (int off = 1; off < 32; off <<= 1) {
            int t = __shfl_up_sync(0xffffffffu, y, off);
            if (lane >= off) y += t;
        }
        wsum[lane] = y;
    }
    __syncthreads();
    if (tid == 0) blockbase = atomicAdd(&g_total, wsum[31]);
    __syncthreads();
    int pre = (wid > 0) ? wsum[wid - 1] : 0;
    if (i < n) g_rowstart[i] = blockbase + pre + x - v;
}

__global__ void edge_fill_k(const int* __restrict__ ei, const float* __restrict__ ew, int E) {
    int e = blockIdx.x * blockDim.x + threadIdx.x;
    if (e >= E) return;
    int r = ei[e];
    int c = ei[E + e];
    int p = g_rowstart[r] + atomicAdd(&g_fill[r], 1);
    float nw = -ew[e] * g_dinv[r] * g_dinv[c];
    g_epack[p] = make_int2(c, __float_as_int(nw));
}

// ---------------------------------------------------------------------------
// Sparse propagation (half state, fp32 accumulate). Thread = (row, 8 features).
// MODE 0: g_Zh  -> g_T1h            (generic T1 = L Z)
// MODE 1: g_T1h -> g_T2h            (generic T2raw = L T1)
// MODE 2: gather g_Zh (=C2), out g_T1h = half(g_T1_f32 + 2*acc)       [layer 0]
// MODE 3: gather g_T1h (=T), out g_H = sp(g_H - toF(g_Zh) + acc + b)
//         + fused BN stats for layer 0                                 [layer 0]
// ---------------------------------------------------------------------------
template<int MODE>
__global__ void prop_h_k(int n, int fi8, const float* __restrict__ bias) {
    __shared__ float ssum[16], ssq[16];
    int flat = threadIdx.y * blockDim.x + threadIdx.x;
    if (MODE == 3) {
        if (flat < 16) { ssum[flat] = 0.f; ssq[flat] = 0.f; }
        __syncthreads();
    }
    int row = blockIdx.x * blockDim.y + threadIdx.y;
    if (row >= n) return;
    const int4* Zin = (const int4*)((MODE == 0 || MODE == 2) ? g_Zh : g_T1h);
    int xf = threadIdx.x;
    int s = g_rowstart[row];
    int e = s + g_cnt[row];
    float acc[8];
#pragma unroll
    for (int j = 0; j < 8; j++) acc[j] = 0.f;
    int i = s;
    for (; i + 4 <= e; i += 4) {
        int2 e0 = g_epack[i], e1 = g_epack[i + 1], e2 = g_epack[i + 2], e3 = g_epack[i + 3];
        int4 v0 = Zin[e0.x * fi8 + xf];
        int4 v1 = Zin[e1.x * fi8 + xf];
        int4 v2 = Zin[e2.x * fi8 + xf];
        int4 v3 = Zin[e3.x * fi8 + xf];
        float w0 = __int_as_float(e0.y), w1 = __int_as_float(e1.y);
        float w2 = __int_as_float(e2.y), w3 = __int_as_float(e3.y);
        const __half2* h0 = (const __half2*)&v0;
        const __half2* h1 = (const __half2*)&v1;
        const __half2* h2 = (const __half2*)&v2;
        const __half2* h3 = (const __half2*)&v3;
#pragma unroll
        for (int j = 0; j < 4; j++) {
            float2 f0 = __half22float2(h0[j]);
            float2 f1 = __half22float2(h1[j]);
            float2 f2 = __half22float2(h2[j]);
            float2 f3 = __half22float2(h3[j]);
            acc[2*j]   = fmaf(w0, f0.x, acc[2*j]);   acc[2*j+1] = fmaf(w0, f0.y, acc[2*j+1]);
            acc[2*j]   = fmaf(w1, f1.x, acc[2*j]);   acc[2*j+1] = fmaf(w1, f1.y, acc[2*j+1]);
            acc[2*j]   = fmaf(w2, f2.x, acc[2*j]);   acc[2*j+1] = fmaf(w2, f2.y, acc[2*j+1]);
            acc[2*j]   = fmaf(w3, f3.x, acc[2*j]);   acc[2*j+1] = fmaf(w3, f3.y, acc[2*j+1]);
        }
    }
    for (; i < e; i++) {
        int2 e0 = g_epack[i];
        int4 v0 = Zin[e0.x * fi8 + xf];
        float w0 = __int_as_float(e0.y);
        const __half2* h0 = (const __half2*)&v0;
#pragma unroll
        for (int j = 0; j < 4; j++) {
            float2 f0 = __half22float2(h0[j]);
            acc[2*j]   = fmaf(w0, f0.x, acc[2*j]);
            acc[2*j+1] = fmaf(w0, f0.y, acc[2*j+1]);
        }
    }
    int idx = row * fi8 + xf;
    if (MODE == 0 || MODE == 1) {
        int4 o; __half2* op = (__half2*)&o;
#pragma unroll
        for (int j = 0; j < 4; j++) op[j] = __floats2half2_rn(acc[2*j], acc[2*j+1]);
        ((int4*)(MODE == 0 ? g_T1h : g_T2h))[idx] = o;
    } else if (MODE == 2) {
        // T = C1 + 2 * acc   (C1 fp32 pointwise)
        int fbase = row * (fi8 * 2) + xf * 2;
        float4 c1a = ((const float4*)g_T1)[fbase];
        float4 c1b = ((const float4*)g_T1)[fbase + 1];
        float cv[8] = {c1a.x, c1a.y, c1a.z, c1a.w, c1b.x, c1b.y, c1b.z, c1b.w};
        int4 o; __half2* op = (__half2*)&o;
#pragma unroll
        for (int j = 0; j < 4; j++)
            op[j] = __floats2half2_rn(cv[2*j] + 2.f*acc[2*j], cv[2*j+1] + 2.f*acc[2*j+1]);
        ((int4*)g_T1h)[idx] = o;
    } else {
        // H = softplus(C0 - C2 + acc + b), fused layer-0 BN stats
        int fbase = row * (fi8 * 2) + xf * 2;
        float4 h0 = ((const float4*)g_H)[fbase];
        float4 h1 = ((const float4*)g_H)[fbase + 1];
        float hv[8] = {h0.x, h0.y, h0.z, h0.w, h1.x, h1.y, h1.z, h1.w};
        int4 vz = ((const int4*)g_Zh)[idx];
        const __half2* hz = (const __half2*)&vz;
        float4 b0 = ((const float4*)bias)[xf * 2];
        float4 b1 = ((const float4*)bias)[xf * 2 + 1];
        float bv[8] = {b0.x, b0.y, b0.z, b0.w, b1.x, b1.y, b1.z, b1.w};
        float ov[8];
#pragma unroll
        for (int j = 0; j < 4; j++) {
            float2 fz = __half22float2(hz[j]);
            ov[2*j]   = softplus_f(hv[2*j]   - fz.x + acc[2*j]   + bv[2*j]);
            ov[2*j+1] = softplus_f(hv[2*j+1] - fz.y + acc[2*j+1] + bv[2*j+1]);
        }
        ((float4*)g_H)[fbase]     = make_float4(ov[0], ov[1], ov[2], ov[3]);
        ((float4*)g_H)[fbase + 1] = make_float4(ov[4], ov[5], ov[6], ov[7]);
#pragma unroll
        for (int j = 0; j < 8; j++) {
            atomicAdd(&ssum[xf * 8 + j], ov[j]);
            atomicAdd(&ssq [xf * 8 + j], ov[j] * ov[j]);
        }
        __syncthreads();
        if (flat < 16) {
            atomicAdd(&g_bnsum[flat], ssum[flat]);
            atomicAdd(&g_bnsq [flat], ssq[flat]);
        }
    }
}

// ---------------------------------------------------------------------------
// Layer-0 commuted GEMM: C0 = x@W0 -> g_H (fp32), C1 = x@W1 -> g_T1 (fp32),
// C2 = x@W2 -> g_Zh (half).  FI=128, per-mat FO=16.
// ---------------------------------------------------------------------------
__global__ void __launch_bounds__(128) cheb_gemm0_k(
    const float* __restrict__ x, const float* __restrict__ W, int n)
{
    constexpr int CG = 4, RPI = 32, RM = 4, BM = RPI * RM;   // BM = 128
    const int cg = threadIdx.x % CG, r0 = threadIdx.x / CG;
    const int rowbase = blockIdx.x * BM;
    const ulonglong2* Wp = (const ulonglong2*)W;   // [3][128][4] of ull2
    const float4* X4 = (const float4*)x;

    ull acc0[RM][2], acc1[RM][2], acc2[RM][2];
    int rows[RM]; bool vld[RM];
#pragma unroll
    for (int r = 0; r < RM; r++) {
        acc0[r][0] = acc0[r][1] = 0ull;
        acc1[r][0] = acc1[r][1] = 0ull;
        acc2[r][0] = acc2[r][1] = 0ull;
        rows[r] = rowbase + r0 + r * RPI;
        vld[r]  = rows[r] < n;
    }

    for (int k0 = 0; k0 < 128; k0 += 4) {
        ulonglong2 w0[4], w1[4], w2[4];
#pragma unroll
        for (int kk = 0; kk < 4; kk++) {
            int wi = (k0 + kk) * CG + cg;
            w0[kk] = Wp[wi];
            w1[kk] = Wp[512 + wi];
            w2[kk] = Wp[1024 + wi];
        }
#pragma unroll
        for (int r = 0; r < RM; r++) {
            float4 z4 = make_float4(0.f, 0.f, 0.f, 0.f);
            if (vld[r]) z4 = X4[rows[r] * 32 + (k0 >> 2)];
            float zz[4] = {z4.x, z4.y, z4.z, z4.w};
#pragma unroll
            for (int kk = 0; kk < 4; kk++) {
                ull a2 = bc2(zz[kk]);
                fma2(acc0[r][0], a2, w0[kk].x); fma2(acc0[r][1], a2, w0[kk].y);
                fma2(acc1[r][0], a2, w1[kk].x); fma2(acc1[r][1], a2, w1[kk].y);
                fma2(acc2[r][0], a2, w2[kk].x); fma2(acc2[r][1], a2, w2[kk].y);
            }
        }
    }

#pragma unroll
    for (int r = 0; r < RM; r++) {
        if (!vld[r]) continue;
        int off = rows[r] * CG + cg;
        F2U l, h;
        l.u = acc0[r][0]; h.u = acc0[r][1];
        ((float4*)g_H )[off] = make_float4(l.f.x, l.f.y, h.f.x, h.f.y);
        l.u = acc1[r][0]; h.u = acc1[r][1];
        ((float4*)g_T1)[off] = make_float4(l.f.x, l.f.y, h.f.x, h.f.y);
        l.u = acc2[r][0]; h.u = acc2[r][1];
        H2I p0, p1;
        p0.h = __floats2half2_rn(l.f.x, l.f.y);
        p1.h = __floats2half2_rn(h.f.x, h.f.y);
        ((int2*)g_Zh)[off] = make_int2(p0.i, p1.i);
    }
}

// ---------------------------------------------------------------------------
// SIMT Chebyshev combine GEMM (layers 1-2), f32x2 packed, half inputs,
// fused BN stats:  H = Z W0 + T1 W1 + (2 T2raw - Z) W2 + b  (+ softplus)
// ---------------------------------------------------------------------------
template<int FI, int FO, int RM, int THREADS, bool ACT>
__global__ void __launch_bounds__(THREADS) cheb_gemm2_k(
    const float* __restrict__ W, const float* __restrict__ b, int n, int lidx)
{
    constexpr int CG = FO / 4;
    constexpr int RPI = THREADS / CG;
    constexpr int BM = RPI * RM;
    __shared__ float ssum[FO], ssq[FO];
    const int tid = threadIdx.x;
    const int cg = tid % CG, r0 = tid / CG;
    const int rowbase = blockIdx.x * BM;
    if (tid < FO) { ssum[tid] = 0.f; ssq[tid] = 0.f; }
    __syncthreads();

    const ulonglong2* Wp = (const ulonglong2*)W;   // [3][FI][CG] of ull2
    const int2* Zh = (const int2*)g_Zh;
    const int2* Ah = (const int2*)g_T1h;
    const int2* Ph = (const int2*)g_T2h;

    ulonglong2 bb = ((const ulonglong2*)b)[cg];
    ull acc[RM][2];
    int rows[RM]; bool vld[RM];
#pragma unroll
    for (int r = 0; r < RM; r++) {
        acc[r][0] = bb.x; acc[r][1] = bb.y;
        rows[r] = rowbase + r0 + r * RPI;
        vld[r]  = rows[r] < n;
    }

    for (int k0 = 0; k0 < FI; k0 += 4) {
        ulonglong2 w0[4], w1[4], w2[4];
#pragma unroll
        for (int kk = 0; kk < 4; kk++) {
            int wi = (k0 + kk) * CG + cg;
            w0[kk] = Wp[wi];
            w1[kk] = Wp[FI * CG + wi];
            w2[kk] = Wp[2 * FI * CG + wi];
        }
#pragma unroll
        for (int r = 0; r < RM; r++) {
            float zz[4] = {0.f, 0.f, 0.f, 0.f};
            float tt[4] = {0.f, 0.f, 0.f, 0.f};
            float uu[4] = {0.f, 0.f, 0.f, 0.f};
            if (vld[r]) {
                int off = rows[r] * (FI / 4) + (k0 >> 2);
                int2 vz = Zh[off], va = Ah[off], vp = Ph[off];
                H2I u;
                u.i = vz.x; float2 z0 = __half22float2(u.h);
                u.i = vz.y; float2 z1 = __half22float2(u.h);
                u.i = va.x; float2 a0 = __half22float2(u.h);
                u.i = va.y; float2 a1 = __half22float2(u.h);
                u.i = vp.x; float2 p0 = __half22float2(u.h);
                u.i = vp.y; float2 p1 = __half22float2(u.h);
                zz[0] = z0.x; zz[1] = z0.y; zz[2] = z1.x; zz[3] = z1.y;
                tt[0] = a0.x; tt[1] = a0.y; tt[2] = a1.x; tt[3] = a1.y;
                uu[0] = 2.f*p0.x - z0.x; uu[1] = 2.f*p0.y - z0.y;
                uu[2] = 2.f*p1.x - z1.x; uu[3] = 2.f*p1.y - z1.y;
            }
#pragma unroll
            for (int kk = 0; kk < 4; kk++) {
                ull a2 = bc2(zz[kk]);
                fma2(acc[r][0], a2, w0[kk].x); fma2(acc[r][1], a2, w0[kk].y);
                ull t2 = bc2(tt[kk]);
                fma2(acc[r][0], t2, w1[kk].x); fma2(acc[r][1], t2, w1[kk].y);
                ull u2 = bc2(uu[kk]);
                fma2(acc[r][0], u2, w2[kk].x); fma2(acc[r][1], u2, w2[kk].y);
            }
        }
    }

    float ls[4] = {0.f, 0.f, 0.f, 0.f}, lq[4] = {0.f, 0.f, 0.f, 0.f};
#pragma unroll
    for (int r = 0; r < RM; r++) {
        if (!vld[r]) continue;
        F2U l, h; l.u = acc[r][0]; h.u = acc[r][1];
        float4 o = make_float4(l.f.x, l.f.y, h.f.x, h.f.y);
        if (ACT) {
            o.x = softplus_f(o.x); o.y = softplus_f(o.y);
            o.z = softplus_f(o.z); o.w = softplus_f(o.w);
        }
        ((float4*)g_H)[rows[r] * CG + cg] = o;
        ls[0] += o.x; ls[1] += o.y; ls[2] += o.z; ls[3] += o.w;
        lq[0] = fmaf(o.x, o.x, lq[0]); lq[1] = fmaf(o.y, o.y, lq[1]);
        lq[2] = fmaf(o.z, o.z, lq[2]); lq[3] = fmaf(o.w, o.w, lq[3]);
    }
#pragma unroll
    for (int j = 0; j < 4; j++) {
        atomicAdd(&ssum[cg * 4 + j], ls[j]);
        atomicAdd(&ssq [cg * 4 + j], lq[j]);
    }
    __syncthreads();
    if (tid < FO) {
        atomicAdd(&g_bnsum[lidx * 256 + tid], ssum[tid]);
        atomicAdd(&g_bnsq [lidx * 256 + tid], ssq[tid]);
    }
}

// ---------------------------------------------------------------------------
// Tensor-core (tf32 mma.sync) Chebyshev combine GEMM, layers 3-4.
// A operands from half buffers. Block tile 128x64, 8 warps (4x2), m16n8k8.
// ACT (layer 3): softplus + fused BN stats, writes g_H.
// POOL (layer 4): NO g_H write — per-block smem pooling (max/sum per graph),
//                 merged into g_poolmax/g_poolsum with global atomics.
// ---------------------------------------------------------------------------
template<int FI, int FO, bool ACT, bool POOL>
__global__ void __launch_bounds__(256) cheb_mma_k(
    const float* __restrict__ W, const float* __restrict__ bias, int n, int lidx,
    const int* __restrict__ bi)
{
    constexpr int BM = 128, BN = 64, KC = 16;
    constexpr int APAD = 136;
    constexpr int BPAD = 72;
    constexpr int PSLOTS = 8;
    __shared__ unsigned int As[KC][APAD];
    __shared__ unsigned int Bs[KC][BPAD];
    __shared__ float ssum[BN], ssq[BN];
    __shared__ int   pmax[POOL ? PSLOTS * BN : 1];
    __shared__ float psum[POOL ? PSLOTS * BN : 1];

    const int tid  = threadIdx.x;
    const int lane = tid & 31, wid = tid >> 5;
    const int wm = wid & 3, wn = wid >> 2;
    const int g = lane >> 2, tig = lane & 3;
    const int row0 = blockIdx.x * BM;
    const int n0   = blockIdx.y * BN;

    if (ACT) {
        if (tid < BN) { ssum[tid] = 0.f; ssq[tid] = 0.f; }
    }

    float c[2][4][4];
#pragma unroll
    for (int mt = 0; mt < 2; mt++)
#pragma unroll
        for (int nt = 0; nt < 4; nt++)
#pragma unroll
            for (int j = 0; j < 4; j++) c[mt][nt][j] = 0.f;

    const int lrow = tid & 127;
    const int lcol = (tid >> 7) * 8;
    const int grow = row0 + lrow;
    const bool lvalid = grow < n;
    const int bk = tid >> 4;
    const int bn = (tid & 15) * 4;

    for (int seg = 0; seg < 3; seg++) {
        const float* Wseg = W + seg * FI * FO;
        for (int kb = 0; kb < FI; kb += KC) {
            float f[8];
#pragma unroll
            for (int j = 0; j < 8; j++) f[j] = 0.f;
            if (lvalid) {
                int base = (grow * FI + kb + lcol) >> 3;
                if (seg == 0) {
                    int4 v = ((const int4*)g_Zh)[base];
                    const __half2* hp = (const __half2*)&v;
#pragma unroll
                    for (int j = 0; j < 4; j++) {
                        float2 ff = __half22float2(hp[j]);
                        f[2*j] = ff.x; f[2*j+1] = ff.y;
                    }
                } else if (seg == 1) {
                    int4 v = ((const int4*)g_T1h)[base];
                    const __half2* hp = (const __half2*)&v;
#pragma unroll
                    for (int j = 0; j < 4; j++) {
                        float2 ff = __half22float2(hp[j]);
                        f[2*j] = ff.x; f[2*j+1] = ff.y;
                    }
                } else {
                    int4 vp = ((const int4*)g_T2h)[base];
                    int4 vz = ((const int4*)g_Zh)[base];
                    const __half2* hp = (const __half2*)&vp;
                    const __half2* hz = (const __half2*)&vz;
#pragma unroll
                    for (int j = 0; j < 4; j++) {
                        float2 fp = __half22float2(hp[j]);
                        float2 fz = __half22float2(hz[j]);
                        f[2*j]   = 2.f*fp.x - fz.x;
                        f[2*j+1] = 2.f*fp.y - fz.y;
                    }
                }
            }
#pragma unroll
            for (int j = 0; j < 8; j++) As[lcol + j][lrow] = tf32_of(f[j]);
            {
                float4 w4 = *(const float4*)(Wseg + (kb + bk) * FO + n0 + bn);
                Bs[bk][bn + 0] = tf32_of(w4.x);
                Bs[bk][bn + 1] = tf32_of(w4.y);
                Bs[bk][bn + 2] = tf32_of(w4.z);
                Bs[bk][bn + 3] = tf32_of(w4.w);
            }
            __syncthreads();
#pragma unroll
            for (int k8 = 0; k8 < KC; k8 += 8) {
                unsigned int af[2][4];
#pragma unroll
                for (int mt = 0; mt < 2; mt++) {
                    int r = wm * 32 + mt * 16 + g;
                    af[mt][0] = As[k8 + tig    ][r];
                    af[mt][1] = As[k8 + tig    ][r + 8];
                    af[mt][2] = As[k8 + tig + 4][r];
                    af[mt][3] = As[k8 + tig + 4][r + 8];
                }
                unsigned int bf[4][2];
#pragma unroll
                for (int nt = 0; nt < 4; nt++) {
                    int cc = wn * 32 + nt * 8 + g;
                    bf[nt][0] = Bs[k8 + tig    ][cc];
                    bf[nt][1] = Bs[k8 + tig + 4][cc];
                }
#pragma unroll
                for (int mt = 0; mt < 2; mt++)
#pragma unroll
                    for (int nt = 0; nt < 4; nt++)
                        mma_tf32(c[mt][nt][0], c[mt][nt][1], c[mt][nt][2], c[mt][nt][3],
                                 af[mt][0], af[mt][1], af[mt][2], af[mt][3],
                                 bf[nt][0], bf[nt][1]);
            }
            __syncthreads();
        }
    }

    if (!POOL) {
        // ---- layer-3 epilogue: softplus + H write + fused BN stats ----
        float ls[4][2], lq[4][2];
        if (ACT) {
#pragma unroll
            for (int nt = 0; nt < 4; nt++) {
                ls[nt][0] = ls[nt][1] = 0.f;
                lq[nt][0] = lq[nt][1] = 0.f;
            }
        }
#pragma unroll
        for (int mt = 0; mt < 2; mt++) {
            int r_lo = row0 + wm * 32 + mt * 16 + g;
            int r_hi = r_lo + 8;
#pragma unroll
            for (int nt = 0; nt < 4; nt++) {
                int col = n0 + wn * 32 + nt * 8 + 2 * tig;
                float b0 = bias[col], b1 = bias[col + 1];
                float o0 = c[mt][nt][0] + b0, o1 = c[mt][nt][1] + b1;
                float o2 = c[mt][nt][2] + b0, o3 = c[mt][nt][3] + b1;
                if (ACT) {
                    o0 = softplus_f(o0); o1 = softplus_f(o1);
                    o2 = softplus_f(o2); o3 = softplus_f(o3);
                }
                if (r_lo < n) {
                    *(float2*)&g_H[r_lo * FO + col] = make_float2(o0, o1);
                    if (ACT) {
                        ls[nt][0] += o0; ls[nt][1] += o1;
                        lq[nt][0] = fmaf(o0, o0, lq[nt][0]);
                        lq[nt][1] = fmaf(o1, o1, lq[nt][1]);
                    }
                }
                if (r_hi < n) {
                    *(float2*)&g_H[r_hi * FO + col] = make_float2(o2, o3);
                    if (ACT) {
                        ls[nt][0] += o2; ls[nt][1] += o3;
                        lq[nt][0] = fmaf(o2, o2, lq[nt][0]);
                        lq[nt][1] = fmaf(o3, o3, lq[nt][1]);
                    }
                }
            }
        }
        if (ACT) {
            __syncthreads();
#pragma unroll
            for (int nt = 0; nt < 4; nt++) {
                int lc = wn * 32 + nt * 8 + 2 * tig;
                atomicAdd(&ssum[lc],     ls[nt][0]);
                atomicAdd(&ssum[lc + 1], ls[nt][1]);
                atomicAdd(&ssq [lc],     lq[nt][0]);
                atomicAdd(&ssq [lc + 1], lq[nt][1]);
            }
            __syncthreads();
            if (tid < BN) {
                atomicAdd(&g_bnsum[lidx * 256 + n0 + tid], ssum[tid]);
                atomicAdd(&g_bnsq [lidx * 256 + n0 + tid], ssq[tid]);
            }
        }
    } else {
        // ---- layer-4 epilogue: fused graph pooling (no H write) ----
        for (int i = tid; i < PSLOTS * BN; i += 256) { pmax[i] = INT_MIN; psum[i] = 0.f; }
        __syncthreads();
        const int gbase = bi[(row0 < n) ? row0 : (n - 1)];
        // thread's 4 rows (ascending): wm*32 + {g, g+8, g+16, g+24} + row0
        float vmax[8], vsum[8];
        int cur = -1;
#pragma unroll
        for (int k = 0; k < 4; k++) {
            int mt = k >> 1;
            int hi = k & 1;
            int r = row0 + wm * 32 + mt * 16 + g + (hi ? 8 : 0);
            if (r >= n) continue;
            int sl = bi[r] - gbase;
            if (sl != cur) {
                if (cur >= 0) {
#pragma unroll
                    for (int nt = 0; nt < 4; nt++) {
                        int lc = wn * 32 + nt * 8 + 2 * tig;
                        atomicMax(&pmax[cur * BN + lc],     fmap_f(vmax[2*nt]));
                        atomicMax(&pmax[cur * BN + lc + 1], fmap_f(vmax[2*nt+1]));
                        atomicAdd(&psum[cur * BN + lc],     vsum[2*nt]);
                        atomicAdd(&psum[cur * BN + lc + 1], vsum[2*nt+1]);
                    }
                }
                cur = sl;
#pragma unroll
                for (int j = 0; j < 8; j++) { vmax[j] = -FLT_MAX; vsum[j] = 0.f; }
            }
#pragma unroll
            for (int nt = 0; nt < 4; nt++) {
                int col = n0 + wn * 32 + nt * 8 + 2 * tig;
                float b0 = bias[col], b1 = bias[col + 1];
                float o0 = c[mt][nt][hi ? 2 : 0] + b0;
                float o1 = c[mt][nt][hi ? 3 : 1] + b1;
                if (cur < PSLOTS) {
                    vmax[2*nt]   = fmaxf(vmax[2*nt],   o0);
                    vmax[2*nt+1] = fmaxf(vmax[2*nt+1], o1);
                    vsum[2*nt]   += o0;
                    vsum[2*nt+1] += o1;
                } else {
                    // rare fallback: graph slot beyond smem window
                    int gg = bi[r];
                    atomicMax(&g_poolmax[gg * 256 + col],     fmap_f(o0));
                    atomicMax(&g_poolmax[gg * 256 + col + 1], fmap_f(o1));
                    atomicAdd(&g_poolsum[gg * 256 + col],     o0);
                    atomicAdd(&g_poolsum[gg * 256 + col + 1], o1);
                }
            }
        }
        if (cur >= 0 && cur < PSLOTS) {
#pragma unroll
            for (int nt = 0; nt < 4; nt++) {
                int lc = wn * 32 + nt * 8 + 2 * tig;
                atomicMax(&pmax[cur * BN + lc],     fmap_f(vmax[2*nt]));
                atomicMax(&pmax[cur * BN + lc + 1], fmap_f(vmax[2*nt+1]));
                atomicAdd(&psum[cur * BN + lc],     vsum[2*nt]);
                atomicAdd(&psum[cur * BN + lc + 1], vsum[2*nt+1]);
            }
        }
        __syncthreads();
        for (int i = tid; i < PSLOTS * BN; i += 256) {
            int sl = i / BN, cidx = i % BN;
            int mv = pmax[i];
            if (mv != INT_MIN) {
                atomicMax(&g_poolmax[(gbase + sl) * 256 + n0 + cidx], mv);
                atomicAdd(&g_poolsum[(gbase + sl) * 256 + n0 + cidx], psum[i]);
            }
        }
    }
}

// ---------------------------------------------------------------------------
// BN finalize+apply (stats already accumulated by producer kernels)
// ---------------------------------------------------------------------------
__global__ void bn_apply_h_k(int total4, int fo,
                             const float* __restrict__ gma,
                             const float* __restrict__ beta, int l, int n) {
    __shared__ float s_sc[256], s_sh[256];
    int tid = threadIdx.x;
    if (tid < fo) {
        float inv_n = 1.f / (float)n;
        float m = g_bnsum[l * 256 + tid] * inv_n;
        float v = g_bnsq[l * 256 + tid] * inv_n - m * m;
        float sc = gma[tid] * rsqrtf(fmaxf(v, 0.f) + 1e-5f);
        s_sc[tid] = sc;
        s_sh[tid] = beta[tid] - m * sc;
    }
    __syncthreads();
    int fo4 = fo >> 2;
    for (int i = blockIdx.x * blockDim.x + tid; i < total4;
         i += gridDim.x * blockDim.x) {
        float4 h = ((const float4*)g_H)[i];
        int f = (i % fo4) * 4;
        H2I a, b;
        a.h = __floats2half2_rn(fmaf(h.x, s_sc[f],     s_sh[f]),
                                fmaf(h.y, s_sc[f + 1], s_sh[f + 1]));
        b.h = __floats2half2_rn(fmaf(h.z, s_sc[f + 2], s_sh[f + 2]),
                                fmaf(h.w, s_sc[f + 3], s_sh[f + 3]));
        ((int2*)g_Zh)[i] = make_int2(a.i, b.i);
    }
}

// ---------------------------------------------------------------------------
// Pool init + segment bounds; dense head
// ---------------------------------------------------------------------------
__global__ void pool_setup_k(const int* __restrict__ batch, int n, int G) {
    int i = blockIdx.x * blockDim.x + threadIdx.x;
    if (i < G * 256) { g_poolmax[i] = INT_MIN; g_poolsum[i] = 0.f; }
    if (i <= G) {
        if (i == G) { g_segstart[G] = n; }
        else {
            int lo = 0, hi = n;
            while (lo < hi) {
                int mid = (lo + hi) >> 1;
                if (batch[mid] < i) lo = mid + 1; else hi = mid;
            }
            g_segstart[i] = lo;
        }
    }
}

__global__ void dense_k(const float* __restrict__ Wd, const float* __restrict__ bd,
                        float* __restrict__ out) {
    __shared__ float sh[4][128];
    int g = blockIdx.x, tid = threadIdx.x;
    int s = g_segstart[g], e = g_segstart[g + 1];
    float cnt = fmaxf((float)(e - s), 1.f);
    float a[4] = {0.f, 0.f, 0.f, 0.f};
    for (int k = tid; k < 512; k += 128) {
        float pv;
        if (k < 256) {
            int key = g_poolmax[g * 256 + k];
            pv = (key == INT_MIN) ? 0.f : funmap_f(key);
        } else {
            pv = g_poolsum[g * 256 + (k - 256)] / cnt;
        }
#pragma unroll
        for (int j = 0; j < 4; j++) a[j] = fmaf(pv, Wd[k * 4 + j], a[j]);
    }
#pragma unroll
    for (int j = 0; j < 4; j++) sh[j][tid] = a[j];
    __syncthreads();
    for (int off = 64; off >= 1; off >>= 1) {
        if (tid < off) {
#pragma unroll
            for (int j = 0; j < 4; j++) sh[j][tid] += sh[j][tid + off];
        }
        __syncthreads();
    }
    if (tid == 0) {
        float l[4];
#pragma unroll
        for (int j = 0; j < 4; j++) l[j] = sh[j][0] + bd[j];
        float m = fmaxf(fmaxf(l[0], l[1]), fmaxf(l[2], l[3]));
        float se = 0.f;
#pragma unroll
        for (int j = 0; j < 4; j++) se += expf(l[j] - m);
        float lse = m + logf(se);
#pragma unroll
        for (int j = 0; j < 4; j++) out[g * 4 + j] = l[j] - lse;
    }
}

// ---------------------------------------------------------------------------
// Host launcher
// ---------------------------------------------------------------------------
extern "C" void kernel_launch(void* const* d_in, const int* in_sizes, int n_in,
                              void* d_out, int out_size) {
    const float *x, *ew, *W[5], *b[5], *gm[4], *be[4], *Wd, *bd;
    const int *ei, *bi;

    bool setup_order = (in_sizes[2] > 1000000);
    if (setup_order) {
        x  = (const float*)d_in[0];
        ew = (const float*)d_in[1];
        ei = (const int*)  d_in[2];
        bi = (const int*)  d_in[3];
        int p = 4;
        for (int l = 0; l < 5; l++) {
            W[l] = (const float*)d_in[p++];
            b[l] = (const float*)d_in[p++];
            if (l < 4) { gm[l] = (const float*)d_in[p++]; be[l] = (const float*)d_in[p++]; }
        }
        Wd = (const float*)d_in[p++];
        bd = (const float*)d_in[p++];
    } else {
        x  = (const float*)d_in[0];
        ew = (const float*)d_in[1];
        int p = 2;
        for (int l = 0; l < 5; l++) {
            W[l] = (const float*)d_in[p++];
            b[l] = (const float*)d_in[p++];
            if (l < 4) { gm[l] = (const float*)d_in[p++]; be[l] = (const float*)d_in[p++]; }
        }
        Wd = (const float*)d_in[p++];
        bd = (const float*)d_in[p++];
        ei = (const int*)d_in[p++];
        bi = (const int*)d_in[p++];
    }

    const int n = in_sizes[0] / 128;
    const int E = in_sizes[1];
    const int G = out_size / 4;     // 64
    float* out = (float*)d_out;

    // side stream (created once; graph-capture forks/joins via events)
    static cudaStream_t s2 = nullptr;
    static cudaEvent_t evFork = nullptr, evJoin = nullptr;
    if (!s2) {
        cudaStreamCreateWithFlags(&s2, cudaStreamNonBlocking);
        cudaEventCreateWithFlags(&evFork, cudaEventDisableTiming);
        cudaEventCreateWithFlags(&evJoin, cudaEventDisableTiming);
    }

    // fork: layer-0 GEMM + pool setup run parallel to the CSR build
    cudaEventRecord(evFork, 0);
    cudaStreamWaitEvent(s2, evFork, 0);
    cheb_gemm0_k<<<(n + 127) / 128, 128, 0, s2>>>(x, W[0], n);
    pool_setup_k<<<(G * 256 + 255) / 256, 256, 0, s2>>>(bi, n, G);

    // main stream: packed deg/cnt, dinv, CSR build
    zero_init_k<<<(n + 255) / 256, 256>>>(n);
    edge_deg_k<<<(E + 255) / 256, 256>>>(ei, ew, E);
    rowbase_k<<<(n + 1023) / 1024, 1024>>>(n);
    edge_fill_k<<<(E + 255) / 256, 256>>>(ei, ew, E);

    // join
    cudaEventRecord(evJoin, s2);
    cudaStreamWaitEvent(0, evJoin, 0);

    // ---- Layer 0 (commuted; props at width 16, half state; stats fused) ----
    {
        dim3 blk(2, 128);
        int grd = (n + 127) / 128;
        prop_h_k<2><<<grd, blk>>>(n, 2, nullptr);   // T = C1 + 2 L C2  -> g_T1h
        prop_h_k<3><<<grd, blk>>>(n, 2, b[0]);      // H = sp(C0 - C2 + L T + b) + stats
    }
    {
        int total4 = n * 16 / 4;
        int agrid = (total4 + 255) / 256; if (agrid > 2048) agrid = 2048;
        bn_apply_h_k<<<agrid, 256>>>(total4, 16, gm[0], be[0], 0, n);
    }

    // ---- Layers 1-4 (all props on half state; stats fused in producers) ----
    for (int l = 1; l < 5; l++) {
        int gx = (n + 127) / 128;
        int fi8 = (l == 1) ? 2 : (l == 2) ? 4 : (l == 3) ? 8 : 16;
        dim3 blk(fi8, 256 / fi8);
        int grd = (n + blk.y - 1) / blk.y;
        prop_h_k<0><<<grd, blk>>>(n, fi8, nullptr);   // T1h = L Zh
        prop_h_k<1><<<grd, blk>>>(n, fi8, nullptr);   // T2h = L T1h

        switch (l) {
            case 1: cheb_gemm2_k< 16,  32, 4, 128, true ><<<(n + 63) / 64, 128>>>(W[1], b[1], n, 1); break;
            case 2: cheb_gemm2_k< 32,  64, 8, 128, true ><<<(n + 63) / 64, 128>>>(W[2], b[2], n, 2); break;
            case 3: cheb_mma_k< 64, 128, true,  false><<<dim3(gx, 2), 256>>>(W[3], b[3], n, 3, nullptr); break;
            case 4: cheb_mma_k<128, 256, false, true ><<<dim3(gx, 4), 256>>>(W[4], b[4], n, 4, bi); break;
        }

        if (l < 4) {
            const int FO = (l == 1) ? 32 : (l == 2) ? 64 : 128;
            int total4 = n * FO / 4;
            int agrid = (total4 + 255) / 256; if (agrid > 2048) agrid = 2048;
            bn_apply_h_k<<<agrid, 256>>>(total4, FO, gm[l], be[l], l, n);
        }
    }

    // ---- dense head (pooling fused into layer-4 mma) ----
    dense_k<<<G, 128>>>(Wd, bd, out);
}

// round 11
// speedup vs baseline: 1.0633x; 1.0125x over previous
#include <cuda_runtime.h>
#include <cuda_fp16.h>
#include <math.h>
#include <float.h>

// ---------------------------------------------------------------------------
// Problem constants (fixed by the dataset)
// ---------------------------------------------------------------------------
#define NMAX 50048
#define EMAX 1600000
#define GMAXC 64

typedef unsigned long long ull;

// ---------------------------------------------------------------------------
// Scratch (static device globals; no allocation at runtime)
// ---------------------------------------------------------------------------
__device__ ull   g_degcnt[NMAX];
__device__ float g_dinv[NMAX];
__device__ int   g_cnt[NMAX];
__device__ int   g_fill[NMAX];
__device__ int   g_rowstart[NMAX];
__device__ int   g_total;
__device__ int2  g_epack[EMAX];
__device__ float g_T1[NMAX * 16];      // layer-0 C1 (fp32, pointwise reads only)
__device__ float g_H [NMAX * 256];     // fp32 activations (pre-BN)
__device__ __half g_Zh [NMAX * 128];
__device__ __half g_T1h[NMAX * 128];
__device__ __half g_T2h[NMAX * 128];
__device__ float g_bnsum[1024];        // [4 layers][256]
__device__ float g_bnsq [1024];
__device__ int   g_poolmax[GMAXC * 256];
__device__ float g_poolsum[GMAXC * 256];
__device__ int   g_segstart[GMAXC + 1];

// ---------------------------------------------------------------------------
// Helpers
// ---------------------------------------------------------------------------
__device__ __forceinline__ float softplus_f(float x) {
    return fmaxf(x, 0.f) + log1pf(expf(-fabsf(x)));
}

__device__ __forceinline__ int fmap_f(float f) {
    int i = __float_as_int(f);
    return (i < 0) ? (i ^ 0x7FFFFFFF) : i;
}
__device__ __forceinline__ float funmap_f(int k) {
    return __int_as_float((k < 0) ? (k ^ 0x7FFFFFFF) : k);
}

// packed fp32x2 FMA (Blackwell): d = a*b + d per 32-bit lane
__device__ __forceinline__ void fma2(ull &d, ull a, ull b) {
    asm("fma.rn.f32x2 %0, %1, %2, %0;" : "+l"(d) : "l"(a), "l"(b));
}
__device__ __forceinline__ ull bc2(float a) {
    ull r; unsigned int u = __float_as_uint(a);
    asm("mov.b64 %0, {%1, %1};" : "=l"(r) : "r"(u));
    return r;
}
union F2U { ull u; float2 f; };
union H2I { __half2 h; int i; };

__device__ __forceinline__ unsigned int tf32_of(float x) {
    unsigned int u;
    asm("cvt.rna.tf32.f32 %0, %1;" : "=r"(u) : "f"(x));
    return u;
}

__device__ __forceinline__ void mma_tf32(
    float &c0, float &c1, float &c2, float &c3,
    unsigned int a0, unsigned int a1, unsigned int a2, unsigned int a3,
    unsigned int b0, unsigned int b1)
{
    asm volatile(
        "mma.sync.aligned.m16n8k8.row.col.f32.tf32.tf32.f32 "
        "{%0,%1,%2,%3}, {%4,%5,%6,%7}, {%8,%9}, {%0,%1,%2,%3};"
        : "+f"(c0), "+f"(c1), "+f"(c2), "+f"(c3)
        : "r"(a0), "r"(a1), "r"(a2), "r"(a3), "r"(b0), "r"(b1));
}

// ---------------------------------------------------------------------------
// Preprocessing
// ---------------------------------------------------------------------------
__global__ void zero_init_k(int n) {
    int i = blockIdx.x * blockDim.x + threadIdx.x;
    if (i < n) { g_degcnt[i] = 0ull; g_fill[i] = 0; }
    if (i < 1024) { g_bnsum[i] = 0.f; g_bnsq[i] = 0.f; }
    if (i == 0) g_total = 0;
}

// one 64-bit atomic per edge: count in bits[40:], deg-sum as 24-bit fixed point
__global__ void edge_deg_k(const int* __restrict__ ei, const float* __restrict__ ew, int E) {
    int e = blockIdx.x * blockDim.x + threadIdx.x;
    if (e >= E) return;
    int r = ei[e];
    ull v = (1ull << 40) | (ull)__float2uint_rn(ew[e] * 16777216.f);
    atomicAdd(&g_degcnt[r], v);
}

// fused: unpack deg/cnt + dinv + per-block scan + one global atomic per block
__global__ void rowbase_k(int n) {
    __shared__ int wsum[32];
    __shared__ int blockbase;
    int tid = threadIdx.x, lane = tid & 31, wid = tid >> 5;
    int i = blockIdx.x * 1024 + tid;
    int v = 0;
    if (i < n) {
        ull dv = g_degcnt[i];
        v = (int)(dv >> 40);
        float d = (float)(dv & 0xFFFFFFFFFFull) * (1.f / 16777216.f);
        g_dinv[i] = (d > 0.f) ? rsqrtf(d) : 0.f;
        g_cnt[i] = v;
    }
    int x = v;
#pragma unroll
    for (int off = 1; off < 32; off <<= 1) {
        int t = __shfl_up_sync(0xffffffffu, x, off);
        if (lane >= off) x += t;
    }
    if (lane == 31) wsum[wid] = x;
    __syncthreads();
    if (wid == 0) {
        int y = wsum[lane];
#pragma unroll
        for (int off = 1; off < 32; off <<= 1) {
            int t = __shfl_up_sync(0xffffffffu, y, off);
            if (lane >= off) y += t;
        }
        wsum[lane] = y;
    }
    __syncthreads();
    if (tid == 0) blockbase = atomicAdd(&g_total, wsum[31]);
    __syncthreads();
    int pre = (wid > 0) ? wsum[wid - 1] : 0;
    if (i < n) g_rowstart[i] = blockbase + pre + x - v;
}

__global__ void edge_fill_k(const int* __restrict__ ei, const float* __restrict__ ew, int E) {
    int e = blockIdx.x * blockDim.x + threadIdx.x;
    if (e >= E) return;
    int r = ei[e];
    int c = ei[E + e];
    int p = g_rowstart[r] + atomicAdd(&g_fill[r], 1);
    float nw = -ew[e] * g_dinv[r] * g_dinv[c];
    g_epack[p] = make_int2(c, __float_as_int(nw));
}

// ---------------------------------------------------------------------------
// Sparse propagation (half state, fp32 accumulate). Thread = (row, 8 features).
// 8-edge unrolled main loop (MLP 8) with int4 epack pair-loads.
// MODE 0: g_Zh  -> g_T1h            (generic T1 = L Z)
// MODE 1: g_T1h -> g_T2h            (generic T2raw = L T1)
// MODE 2: gather g_Zh (=C2), out g_T1h = half(g_T1_f32 + 2*acc)       [layer 0]
// MODE 3: gather g_T1h (=T), out g_H = sp(g_H - toF(g_Zh) + acc + b)
//         + fused BN stats for layer 0                                 [layer 0]
// ---------------------------------------------------------------------------
template<int MODE>
__global__ void prop_h_k(int n, int fi8, const float* __restrict__ bias) {
    __shared__ float ssum[16], ssq[16];
    int flat = threadIdx.y * blockDim.x + threadIdx.x;
    if (MODE == 3) {
        if (flat < 16) { ssum[flat] = 0.f; ssq[flat] = 0.f; }
        __syncthreads();
    }
    int row = blockIdx.x * blockDim.y + threadIdx.y;
    if (row >= n) return;
    const int4* Zin = (const int4*)((MODE == 0 || MODE == 2) ? g_Zh : g_T1h);
    int xf = threadIdx.x;
    int s = g_rowstart[row];
    int e = s + g_cnt[row];
    float acc[8];
#pragma unroll
    for (int j = 0; j < 8; j++) acc[j] = 0.f;

    int i = s;
    // peel one edge if start is odd (align epack pair loads to 16B)
    if ((i & 1) && i < e) {
        int2 ep = g_epack[i];
        int4 v = Zin[ep.x * fi8 + xf];
        float w = __int_as_float(ep.y);
        const __half2* h = (const __half2*)&v;
#pragma unroll
        for (int j = 0; j < 4; j++) {
            float2 f = __half22float2(h[j]);
            acc[2*j]   = fmaf(w, f.x, acc[2*j]);
            acc[2*j+1] = fmaf(w, f.y, acc[2*j+1]);
        }
        i++;
    }
    // 8-edge unrolled: 4 x int4 epack loads + 8 independent gathers
    for (; i + 8 <= e; i += 8) {
        int4 epA = *(const int4*)&g_epack[i];
        int4 epB = *(const int4*)&g_epack[i + 2];
        int4 epC = *(const int4*)&g_epack[i + 4];
        int4 epD = *(const int4*)&g_epack[i + 6];
        int4 v0 = Zin[epA.x * fi8 + xf];
        int4 v1 = Zin[epA.z * fi8 + xf];
        int4 v2 = Zin[epB.x * fi8 + xf];
        int4 v3 = Zin[epB.z * fi8 + xf];
        int4 v4 = Zin[epC.x * fi8 + xf];
        int4 v5 = Zin[epC.z * fi8 + xf];
        int4 v6 = Zin[epD.x * fi8 + xf];
        int4 v7 = Zin[epD.z * fi8 + xf];
        float w0 = __int_as_float(epA.y), w1 = __int_as_float(epA.w);
        float w2 = __int_as_float(epB.y), w3 = __int_as_float(epB.w);
        float w4 = __int_as_float(epC.y), w5 = __int_as_float(epC.w);
        float w6 = __int_as_float(epD.y), w7 = __int_as_float(epD.w);
        const __half2* h0 = (const __half2*)&v0;
        const __half2* h1 = (const __half2*)&v1;
        const __half2* h2 = (const __half2*)&v2;
        const __half2* h3 = (const __half2*)&v3;
        const __half2* h4 = (const __half2*)&v4;
        const __half2* h5 = (const __half2*)&v5;
        const __half2* h6 = (const __half2*)&v6;
        const __half2* h7 = (const __half2*)&v7;
#pragma unroll
        for (int j = 0; j < 4; j++) {
            float2 f0 = __half22float2(h0[j]);
            float2 f1 = __half22float2(h1[j]);
            float2 f2 = __half22float2(h2[j]);
            float2 f3 = __half22float2(h3[j]);
            acc[2*j]   = fmaf(w0, f0.x, acc[2*j]);   acc[2*j+1] = fmaf(w0, f0.y, acc[2*j+1]);
            acc[2*j]   = fmaf(w1, f1.x, acc[2*j]);   acc[2*j+1] = fmaf(w1, f1.y, acc[2*j+1]);
            acc[2*j]   = fmaf(w2, f2.x, acc[2*j]);   acc[2*j+1] = fmaf(w2, f2.y, acc[2*j+1]);
            acc[2*j]   = fmaf(w3, f3.x, acc[2*j]);   acc[2*j+1] = fmaf(w3, f3.y, acc[2*j+1]);
            float2 f4 = __half22float2(h4[j]);
            float2 f5 = __half22float2(h5[j]);
            float2 f6 = __half22float2(h6[j]);
            float2 f7 = __half22float2(h7[j]);
            acc[2*j]   = fmaf(w4, f4.x, acc[2*j]);   acc[2*j+1] = fmaf(w4, f4.y, acc[2*j+1]);
            acc[2*j]   = fmaf(w5, f5.x, acc[2*j]);   acc[2*j+1] = fmaf(w5, f5.y, acc[2*j+1]);
            acc[2*j]   = fmaf(w6, f6.x, acc[2*j]);   acc[2*j+1] = fmaf(w6, f6.y, acc[2*j+1]);
            acc[2*j]   = fmaf(w7, f7.x, acc[2*j]);   acc[2*j+1] = fmaf(w7, f7.y, acc[2*j+1]);
        }
    }
    // pair tail
    for (; i + 2 <= e; i += 2) {
        int4 epA = *(const int4*)&g_epack[i];
        int4 v0 = Zin[epA.x * fi8 + xf];
        int4 v1 = Zin[epA.z * fi8 + xf];
        float w0 = __int_as_float(epA.y), w1 = __int_as_float(epA.w);
        const __half2* h0 = (const __half2*)&v0;
        const __half2* h1 = (const __half2*)&v1;
#pragma unroll
        for (int j = 0; j < 4; j++) {
            float2 f0 = __half22float2(h0[j]);
            float2 f1 = __half22float2(h1[j]);
            acc[2*j]   = fmaf(w0, f0.x, acc[2*j]);   acc[2*j+1] = fmaf(w0, f0.y, acc[2*j+1]);
            acc[2*j]   = fmaf(w1, f1.x, acc[2*j]);   acc[2*j+1] = fmaf(w1, f1.y, acc[2*j+1]);
        }
    }
    if (i < e) {
        int2 ep = g_epack[i];
        int4 v = Zin[ep.x * fi8 + xf];
        float w = __int_as_float(ep.y);
        const __half2* h = (const __half2*)&v;
#pragma unroll
        for (int j = 0; j < 4; j++) {
            float2 f = __half22float2(h[j]);
            acc[2*j]   = fmaf(w, f.x, acc[2*j]);
            acc[2*j+1] = fmaf(w, f.y, acc[2*j+1]);
        }
    }

    int idx = row * fi8 + xf;
    if (MODE == 0 || MODE == 1) {
        int4 o; __half2* op = (__half2*)&o;
#pragma unroll
        for (int j = 0; j < 4; j++) op[j] = __floats2half2_rn(acc[2*j], acc[2*j+1]);
        ((int4*)(MODE == 0 ? g_T1h : g_T2h))[idx] = o;
    } else if (MODE == 2) {
        // T = C1 + 2 * acc   (C1 fp32 pointwise)
        int fbase = row * (fi8 * 2) + xf * 2;
        float4 c1a = ((const float4*)g_T1)[fbase];
        float4 c1b = ((const float4*)g_T1)[fbase + 1];
        float cv[8] = {c1a.x, c1a.y, c1a.z, c1a.w, c1b.x, c1b.y, c1b.z, c1b.w};
        int4 o; __half2* op = (__half2*)&o;
#pragma unroll
        for (int j = 0; j < 4; j++)
            op[j] = __floats2half2_rn(cv[2*j] + 2.f*acc[2*j], cv[2*j+1] + 2.f*acc[2*j+1]);
        ((int4*)g_T1h)[idx] = o;
    } else {
        // H = softplus(C0 - C2 + acc + b), fused layer-0 BN stats
        int fbase = row * (fi8 * 2) + xf * 2;
        float4 h0 = ((const float4*)g_H)[fbase];
        float4 h1 = ((const float4*)g_H)[fbase + 1];
        float hv[8] = {h0.x, h0.y, h0.z, h0.w, h1.x, h1.y, h1.z, h1.w};
        int4 vz = ((const int4*)g_Zh)[idx];
        const __half2* hz = (const __half2*)&vz;
        float4 b0 = ((const float4*)bias)[xf * 2];
        float4 b1 = ((const float4*)bias)[xf * 2 + 1];
        float bv[8] = {b0.x, b0.y, b0.z, b0.w, b1.x, b1.y, b1.z, b1.w};
        float ov[8];
#pragma unroll
        for (int j = 0; j < 4; j++) {
            float2 fz = __half22float2(hz[j]);
            ov[2*j]   = softplus_f(hv[2*j]   - fz.x + acc[2*j]   + bv[2*j]);
            ov[2*j+1] = softplus_f(hv[2*j+1] - fz.y + acc[2*j+1] + bv[2*j+1]);
        }
        ((float4*)g_H)[fbase]     = make_float4(ov[0], ov[1], ov[2], ov[3]);
        ((float4*)g_H)[fbase + 1] = make_float4(ov[4], ov[5], ov[6], ov[7]);
#pragma unroll
        for (int j = 0; j < 8; j++) {
            atomicAdd(&ssum[xf * 8 + j], ov[j]);
            atomicAdd(&ssq [xf * 8 + j], ov[j] * ov[j]);
        }
        __syncthreads();
        if (flat < 16) {
            atomicAdd(&g_bnsum[flat], ssum[flat]);
            atomicAdd(&g_bnsq [flat], ssq[flat]);
        }
    }
}

// ---------------------------------------------------------------------------
// Layer-0 commuted GEMM: C0 = x@W0 -> g_H (fp32), C1 = x@W1 -> g_T1 (fp32),
// C2 = x@W2 -> g_Zh (half).  FI=128, per-mat FO=16.
// ---------------------------------------------------------------------------
__global__ void __launch_bounds__(128) cheb_gemm0_k(
    const float* __restrict__ x, const float* __restrict__ W, int n)
{
    constexpr int CG = 4, RPI = 32, RM = 4, BM = RPI * RM;   // BM = 128
    const int cg = threadIdx.x % CG, r0 = threadIdx.x / CG;
    const int rowbase = blockIdx.x * BM;
    const ulonglong2* Wp = (const ulonglong2*)W;   // [3][128][4] of ull2
    const float4* X4 = (const float4*)x;

    ull acc0[RM][2], acc1[RM][2], acc2[RM][2];
    int rows[RM]; bool vld[RM];
#pragma unroll
    for (int r = 0; r < RM; r++) {
        acc0[r][0] = acc0[r][1] = 0ull;
        acc1[r][0] = acc1[r][1] = 0ull;
        acc2[r][0] = acc2[r][1] = 0ull;
        rows[r] = rowbase + r0 + r * RPI;
        vld[r]  = rows[r] < n;
    }

    for (int k0 = 0; k0 < 128; k0 += 4) {
        ulonglong2 w0[4], w1[4], w2[4];
#pragma unroll
        for (int kk = 0; kk < 4; kk++) {
            int wi = (k0 + kk) * CG + cg;
            w0[kk] = Wp[wi];
            w1[kk] = Wp[512 + wi];
            w2[kk] = Wp[1024 + wi];
        }
#pragma unroll
        for (int r = 0; r < RM; r++) {
            float4 z4 = make_float4(0.f, 0.f, 0.f, 0.f);
            if (vld[r]) z4 = X4[rows[r] * 32 + (k0 >> 2)];
            float zz[4] = {z4.x, z4.y, z4.z, z4.w};
#pragma unroll
            for (int kk = 0; kk < 4; kk++) {
                ull a2 = bc2(zz[kk]);
                fma2(acc0[r][0], a2, w0[kk].x); fma2(acc0[r][1], a2, w0[kk].y);
                fma2(acc1[r][0], a2, w1[kk].x); fma2(acc1[r][1], a2, w1[kk].y);
                fma2(acc2[r][0], a2, w2[kk].x); fma2(acc2[r][1], a2, w2[kk].y);
            }
        }
    }

#pragma unroll
    for (int r = 0; r < RM; r++) {
        if (!vld[r]) continue;
        int off = rows[r] * CG + cg;
        F2U l, h;
        l.u = acc0[r][0]; h.u = acc0[r][1];
        ((float4*)g_H )[off] = make_float4(l.f.x, l.f.y, h.f.x, h.f.y);
        l.u = acc1[r][0]; h.u = acc1[r][1];
        ((float4*)g_T1)[off] = make_float4(l.f.x, l.f.y, h.f.x, h.f.y);
        l.u = acc2[r][0]; h.u = acc2[r][1];
        H2I p0, p1;
        p0.h = __floats2half2_rn(l.f.x, l.f.y);
        p1.h = __floats2half2_rn(h.f.x, h.f.y);
        ((int2*)g_Zh)[off] = make_int2(p0.i, p1.i);
    }
}

// ---------------------------------------------------------------------------
// SIMT Chebyshev combine GEMM (layers 1-2), f32x2 packed, half inputs,
// fused BN stats:  H = Z W0 + T1 W1 + (2 T2raw - Z) W2 + b  (+ softplus)
// ---------------------------------------------------------------------------
template<int FI, int FO, int RM, int THREADS, bool ACT>
__global__ void __launch_bounds__(THREADS) cheb_gemm2_k(
    const float* __restrict__ W, const float* __restrict__ b, int n, int lidx)
{
    constexpr int CG = FO / 4;
    constexpr int RPI = THREADS / CG;
    constexpr int BM = RPI * RM;
    __shared__ float ssum[FO], ssq[FO];
    const int tid = threadIdx.x;
    const int cg = tid % CG, r0 = tid / CG;
    const int rowbase = blockIdx.x * BM;
    if (tid < FO) { ssum[tid] = 0.f; ssq[tid] = 0.f; }
    __syncthreads();

    const ulonglong2* Wp = (const ulonglong2*)W;   // [3][FI][CG] of ull2
    const int2* Zh = (const int2*)g_Zh;
    const int2* Ah = (const int2*)g_T1h;
    const int2* Ph = (const int2*)g_T2h;

    ulonglong2 bb = ((const ulonglong2*)b)[cg];
    ull acc[RM][2];
    int rows[RM]; bool vld[RM];
#pragma unroll
    for (int r = 0; r < RM; r++) {
        acc[r][0] = bb.x; acc[r][1] = bb.y;
        rows[r] = rowbase + r0 + r * RPI;
        vld[r]  = rows[r] < n;
    }

    for (int k0 = 0; k0 < FI; k0 += 4) {
        ulonglong2 w0[4], w1[4], w2[4];
#pragma unroll
        for (int kk = 0; kk < 4; kk++) {
            int wi = (k0 + kk) * CG + cg;
            w0[kk] = Wp[wi];
            w1[kk] = Wp[FI * CG + wi];
            w2[kk] = Wp[2 * FI * CG + wi];
        }
#pragma unroll
        for (int r = 0; r < RM; r++) {
            float zz[4] = {0.f, 0.f, 0.f, 0.f};
            float tt[4] = {0.f, 0.f, 0.f, 0.f};
            float uu[4] = {0.f, 0.f, 0.f, 0.f};
            if (vld[r]) {
                int off = rows[r] * (FI / 4) + (k0 >> 2);
                int2 vz = Zh[off], va = Ah[off], vp = Ph[off];
                H2I u;
                u.i = vz.x; float2 z0 = __half22float2(u.h);
                u.i = vz.y; float2 z1 = __half22float2(u.h);
                u.i = va.x; float2 a0 = __half22float2(u.h);
                u.i = va.y; float2 a1 = __half22float2(u.h);
                u.i = vp.x; float2 p0 = __half22float2(u.h);
                u.i = vp.y; float2 p1 = __half22float2(u.h);
                zz[0] = z0.x; zz[1] = z0.y; zz[2] = z1.x; zz[3] = z1.y;
                tt[0] = a0.x; tt[1] = a0.y; tt[2] = a1.x; tt[3] = a1.y;
                uu[0] = 2.f*p0.x - z0.x; uu[1] = 2.f*p0.y - z0.y;
                uu[2] = 2.f*p1.x - z1.x; uu[3] = 2.f*p1.y - z1.y;
            }
#pragma unroll
            for (int kk = 0; kk < 4; kk++) {
                ull a2 = bc2(zz[kk]);
                fma2(acc[r][0], a2, w0[kk].x); fma2(acc[r][1], a2, w0[kk].y);
                ull t2 = bc2(tt[kk]);
                fma2(acc[r][0], t2, w1[kk].x); fma2(acc[r][1], t2, w1[kk].y);
                ull u2 = bc2(uu[kk]);
                fma2(acc[r][0], u2, w2[kk].x); fma2(acc[r][1], u2, w2[kk].y);
            }
        }
    }

    float ls[4] = {0.f, 0.f, 0.f, 0.f}, lq[4] = {0.f, 0.f, 0.f, 0.f};
#pragma unroll
    for (int r = 0; r < RM; r++) {
        if (!vld[r]) continue;
        F2U l, h; l.u = acc[r][0]; h.u = acc[r][1];
        float4 o = make_float4(l.f.x, l.f.y, h.f.x, h.f.y);
        if (ACT) {
            o.x = softplus_f(o.x); o.y = softplus_f(o.y);
            o.z = softplus_f(o.z); o.w = softplus_f(o.w);
        }
        ((float4*)g_H)[rows[r] * CG + cg] = o;
        ls[0] += o.x; ls[1] += o.y; ls[2] += o.z; ls[3] += o.w;
        lq[0] = fmaf(o.x, o.x, lq[0]); lq[1] = fmaf(o.y, o.y, lq[1]);
        lq[2] = fmaf(o.z, o.z, lq[2]); lq[3] = fmaf(o.w, o.w, lq[3]);
    }
#pragma unroll
    for (int j = 0; j < 4; j++) {
        atomicAdd(&ssum[cg * 4 + j], ls[j]);
        atomicAdd(&ssq [cg * 4 + j], lq[j]);
    }
    __syncthreads();
    if (tid < FO) {
        atomicAdd(&g_bnsum[lidx * 256 + tid], ssum[tid]);
        atomicAdd(&g_bnsq [lidx * 256 + tid], ssq[tid]);
    }
}

// ---------------------------------------------------------------------------
// Tensor-core (tf32 mma.sync) Chebyshev combine GEMM, layers 3-4.
// A operands from half buffers. Block tile 128x64, 8 warps (4x2), m16n8k8.
// ACT (layer 3): softplus + fused BN stats, writes g_H.
// POOL (layer 4): NO g_H write — per-block smem pooling (max/sum per graph),
//                 merged into g_poolmax/g_poolsum with global atomics.
// ---------------------------------------------------------------------------
template<int FI, int FO, bool ACT, bool POOL>
__global__ void __launch_bounds__(256) cheb_mma_k(
    const float* __restrict__ W, const float* __restrict__ bias, int n, int lidx,
    const int* __restrict__ bi)
{
    constexpr int BM = 128, BN = 64, KC = 16;
    constexpr int APAD = 136;
    constexpr int BPAD = 72;
    constexpr int PSLOTS = 8;
    __shared__ unsigned int As[KC][APAD];
    __shared__ unsigned int Bs[KC][BPAD];
    __shared__ float ssum[BN], ssq[BN];
    __shared__ int   pmax[POOL ? PSLOTS * BN : 1];
    __shared__ float psum[POOL ? PSLOTS * BN : 1];

    const int tid  = threadIdx.x;
    const int lane = tid & 31, wid = tid >> 5;
    const int wm = wid & 3, wn = wid >> 2;
    const int g = lane >> 2, tig = lane & 3;
    const int row0 = blockIdx.x * BM;
    const int n0   = blockIdx.y * BN;

    if (ACT) {
        if (tid < BN) { ssum[tid] = 0.f; ssq[tid] = 0.f; }
    }

    float c[2][4][4];
#pragma unroll
    for (int mt = 0; mt < 2; mt++)
#pragma unroll
        for (int nt = 0; nt < 4; nt++)
#pragma unroll
            for (int j = 0; j < 4; j++) c[mt][nt][j] = 0.f;

    const int lrow = tid & 127;
    const int lcol = (tid >> 7) * 8;
    const int grow = row0 + lrow;
    const bool lvalid = grow < n;
    const int bk = tid >> 4;
    const int bn = (tid & 15) * 4;

    for (int seg = 0; seg < 3; seg++) {
        const float* Wseg = W + seg * FI * FO;
        for (int kb = 0; kb < FI; kb += KC) {
            float f[8];
#pragma unroll
            for (int j = 0; j < 8; j++) f[j] = 0.f;
            if (lvalid) {
                int base = (grow * FI + kb + lcol) >> 3;
                if (seg == 0) {
                    int4 v = ((const int4*)g_Zh)[base];
                    const __half2* hp = (const __half2*)&v;
#pragma unroll
                    for (int j = 0; j < 4; j++) {
                        float2 ff = __half22float2(hp[j]);
                        f[2*j] = ff.x; f[2*j+1] = ff.y;
                    }
                } else if (seg == 1) {
                    int4 v = ((const int4*)g_T1h)[base];
                    const __half2* hp = (const __half2*)&v;
#pragma unroll
                    for (int j = 0; j < 4; j++) {
                        float2 ff = __half22float2(hp[j]);
                        f[2*j] = ff.x; f[2*j+1] = ff.y;
                    }
                } else {
                    int4 vp = ((const int4*)g_T2h)[base];
                    int4 vz = ((const int4*)g_Zh)[base];
                    const __half2* hp = (const __half2*)&vp;
                    const __half2* hz = (const __half2*)&vz;
#pragma unroll
                    for (int j = 0; j < 4; j++) {
                        float2 fp = __half22float2(hp[j]);
                        float2 fz = __half22float2(hz[j]);
                        f[2*j]   = 2.f*fp.x - fz.x;
                        f[2*j+1] = 2.f*fp.y - fz.y;
                    }
                }
            }
#pragma unroll
            for (int j = 0; j < 8; j++) As[lcol + j][lrow] = tf32_of(f[j]);
            {
                float4 w4 = *(const float4*)(Wseg + (kb + bk) * FO + n0 + bn);
                Bs[bk][bn + 0] = tf32_of(w4.x);
                Bs[bk][bn + 1] = tf32_of(w4.y);
                Bs[bk][bn + 2] = tf32_of(w4.z);
                Bs[bk][bn + 3] = tf32_of(w4.w);
            }
            __syncthreads();
#pragma unroll
            for (int k8 = 0; k8 < KC; k8 += 8) {
                unsigned int af[2][4];
#pragma unroll
                for (int mt = 0; mt < 2; mt++) {
                    int r = wm * 32 + mt * 16 + g;
                    af[mt][0] = As[k8 + tig    ][r];
                    af[mt][1] = As[k8 + tig    ][r + 8];
                    af[mt][2] = As[k8 + tig + 4][r];
                    af[mt][3] = As[k8 + tig + 4][r + 8];
                }
                unsigned int bf[4][2];
#pragma unroll
                for (int nt = 0; nt < 4; nt++) {
                    int cc = wn * 32 + nt * 8 + g;
                    bf[nt][0] = Bs[k8 + tig    ][cc];
                    bf[nt][1] = Bs[k8 + tig + 4][cc];
                }
#pragma unroll
                for (int mt = 0; mt < 2; mt++)
#pragma unroll
                    for (int nt = 0; nt < 4; nt++)
                        mma_tf32(c[mt][nt][0], c[mt][nt][1], c[mt][nt][2], c[mt][nt][3],
                                 af[mt][0], af[mt][1], af[mt][2], af[mt][3],
                                 bf[nt][0], bf[nt][1]);
            }
            __syncthreads();
        }
    }

    if (!POOL) {
        // ---- layer-3 epilogue: softplus + H write + fused BN stats ----
        float ls[4][2], lq[4][2];
        if (ACT) {
#pragma unroll
            for (int nt = 0; nt < 4; nt++) {
                ls[nt][0] = ls[nt][1] = 0.f;
                lq[nt][0] = lq[nt][1] = 0.f;
            }
        }
#pragma unroll
        for (int mt = 0; mt < 2; mt++) {
            int r_lo = row0 + wm * 32 + mt * 16 + g;
            int r_hi = r_lo + 8;
#pragma unroll
            for (int nt = 0; nt < 4; nt++) {
                int col = n0 + wn * 32 + nt * 8 + 2 * tig;
                float b0 = bias[col], b1 = bias[col + 1];
                float o0 = c[mt][nt][0] + b0, o1 = c[mt][nt][1] + b1;
                float o2 = c[mt][nt][2] + b0, o3 = c[mt][nt][3] + b1;
                if (ACT) {
                    o0 = softplus_f(o0); o1 = softplus_f(o1);
                    o2 = softplus_f(o2); o3 = softplus_f(o3);
                }
                if (r_lo < n) {
                    *(float2*)&g_H[r_lo * FO + col] = make_float2(o0, o1);
                    if (ACT) {
                        ls[nt][0] += o0; ls[nt][1] += o1;
                        lq[nt][0] = fmaf(o0, o0, lq[nt][0]);
                        lq[nt][1] = fmaf(o1, o1, lq[nt][1]);
                    }
                }
                if (r_hi < n) {
                    *(float2*)&g_H[r_hi * FO + col] = make_float2(o2, o3);
                    if (ACT) {
                        ls[nt][0] += o2; ls[nt][1] += o3;
                        lq[nt][0] = fmaf(o2, o2, lq[nt][0]);
                        lq[nt][1] = fmaf(o3, o3, lq[nt][1]);
                    }
                }
            }
        }
        if (ACT) {
            __syncthreads();
#pragma unroll
            for (int nt = 0; nt < 4; nt++) {
                int lc = wn * 32 + nt * 8 + 2 * tig;
                atomicAdd(&ssum[lc],     ls[nt][0]);
                atomicAdd(&ssum[lc + 1], ls[nt][1]);
                atomicAdd(&ssq [lc],     lq[nt][0]);
                atomicAdd(&ssq [lc + 1], lq[nt][1]);
            }
            __syncthreads();
            if (tid < BN) {
                atomicAdd(&g_bnsum[lidx * 256 + n0 + tid], ssum[tid]);
                atomicAdd(&g_bnsq [lidx * 256 + n0 + tid], ssq[tid]);
            }
        }
    } else {
        // ---- layer-4 epilogue: fused graph pooling (no H write) ----
        for (int i = tid; i < PSLOTS * BN; i += 256) { pmax[i] = INT_MIN; psum[i] = 0.f; }
        __syncthreads();
        const int gbase = bi[(row0 < n) ? row0 : (n - 1)];
        // thread's 4 rows (ascending): wm*32 + {g, g+8, g+16, g+24} + row0
        float vmax[8], vsum[8];
        int cur = -1;
#pragma unroll
        for (int k = 0; k < 4; k++) {
            int mt = k >> 1;
            int hi = k & 1;
            int r = row0 + wm * 32 + mt * 16 + g + (hi ? 8 : 0);
            if (r >= n) continue;
            int sl = bi[r] - gbase;
            if (sl != cur) {
                if (cur >= 0) {
#pragma unroll
                    for (int nt = 0; nt < 4; nt++) {
                        int lc = wn * 32 + nt * 8 + 2 * tig;
                        atomicMax(&pmax[cur * BN + lc],     fmap_f(vmax[2*nt]));
                        atomicMax(&pmax[cur * BN + lc + 1], fmap_f(vmax[2*nt+1]));
                        atomicAdd(&psum[cur * BN + lc],     vsum[2*nt]);
                        atomicAdd(&psum[cur * BN + lc + 1], vsum[2*nt+1]);
                    }
                }
                cur = sl;
#pragma unroll
                for (int j = 0; j < 8; j++) { vmax[j] = -FLT_MAX; vsum[j] = 0.f; }
            }
#pragma unroll
            for (int nt = 0; nt < 4; nt++) {
                int col = n0 + wn * 32 + nt * 8 + 2 * tig;
                float b0 = bias[col], b1 = bias[col + 1];
                float o0 = c[mt][nt][hi ? 2 : 0] + b0;
                float o1 = c[mt][nt][hi ? 3 : 1] + b1;
                if (cur < PSLOTS) {
                    vmax[2*nt]   = fmaxf(vmax[2*nt],   o0);
                    vmax[2*nt+1] = fmaxf(vmax[2*nt+1], o1);
                    vsum[2*nt]   += o0;
                    vsum[2*nt+1] += o1;
                } else {
                    // rare fallback: graph slot beyond smem window
                    int gg = bi[r];
                    atomicMax(&g_poolmax[gg * 256 + col],     fmap_f(o0));
                    atomicMax(&g_poolmax[gg * 256 + col + 1], fmap_f(o1));
                    atomicAdd(&g_poolsum[gg * 256 + col],     o0);
                    atomicAdd(&g_poolsum[gg * 256 + col + 1], o1);
                }
            }
        }
        if (cur >= 0 && cur < PSLOTS) {
#pragma unroll
            for (int nt = 0; nt < 4; nt++) {
                int lc = wn * 32 + nt * 8 + 2 * tig;
                atomicMax(&pmax[cur * BN + lc],     fmap_f(vmax[2*nt]));
                atomicMax(&pmax[cur * BN + lc + 1], fmap_f(vmax[2*nt+1]));
                atomicAdd(&psum[cur * BN + lc],     vsum[2*nt]);
                atomicAdd(&psum[cur * BN + lc + 1], vsum[2*nt+1]);
            }
        }
        __syncthreads();
        for (int i = tid; i < PSLOTS * BN; i += 256) {
            int sl = i / BN, cidx = i % BN;
            int mv = pmax[i];
            if (mv != INT_MIN) {
                atomicMax(&g_poolmax[(gbase + sl) * 256 + n0 + cidx], mv);
                atomicAdd(&g_poolsum[(gbase + sl) * 256 + n0 + cidx], psum[i]);
            }
        }
    }
}

// ---------------------------------------------------------------------------
// BN finalize+apply (stats already accumulated by producer kernels)
// ---------------------------------------------------------------------------
__global__ void bn_apply_h_k(int total4, int fo,
                             const float* __restrict__ gma,
                             const float* __restrict__ beta, int l, int n) {
    __shared__ float s_sc[256], s_sh[256];
    int tid = threadIdx.x;
    if (tid < fo) {
        float inv_n = 1.f / (float)n;
        float m = g_bnsum[l * 256 + tid] * inv_n;
        float v = g_bnsq[l * 256 + tid] * inv_n - m * m;
        float sc = gma[tid] * rsqrtf(fmaxf(v, 0.f) + 1e-5f);
        s_sc[tid] = sc;
        s_sh[tid] = beta[tid] - m * sc;
    }
    __syncthreads();
    int fo4 = fo >> 2;
    for (int i = blockIdx.x * blockDim.x + tid; i < total4;
         i += gridDim.x * blockDim.x) {
        float4 h = ((const float4*)g_H)[i];
        int f = (i % fo4) * 4;
        H2I a, b;
        a.h = __floats2half2_rn(fmaf(h.x, s_sc[f],     s_sh[f]),
                                fmaf(h.y, s_sc[f + 1], s_sh[f + 1]));
        b.h = __floats2half2_rn(fmaf(h.z, s_sc[f + 2], s_sh[f + 2]),
                                fmaf(h.w, s_sc[f + 3], s_sh[f + 3]));
        ((int2*)g_Zh)[i] = make_int2(a.i, b.i);
    }
}

// ---------------------------------------------------------------------------
// Pool init + segment bounds; dense head
// ---------------------------------------------------------------------------
__global__ void pool_setup_k(const int* __restrict__ batch, int n, int G) {
    int i = blockIdx.x * blockDim.x + threadIdx.x;
    if (i < G * 256) { g_poolmax[i] = INT_MIN; g_poolsum[i] = 0.f; }
    if (i <= G) {
        if (i == G) { g_segstart[G] = n; }
        else {
            int lo = 0, hi = n;
            while (lo < hi) {
                int mid = (lo + hi) >> 1;
                if (batch[mid] < i) lo = mid + 1; else hi = mid;
            }
            g_segstart[i] = lo;
        }
    }
}

__global__ void dense_k(const float* __restrict__ Wd, const float* __restrict__ bd,
                        float* __restrict__ out) {
    __shared__ float sh[4][128];
    int g = blockIdx.x, tid = threadIdx.x;
    int s = g_segstart[g], e = g_segstart[g + 1];
    float cnt = fmaxf((float)(e - s), 1.f);
    float a[4] = {0.f, 0.f, 0.f, 0.f};
    for (int k = tid; k < 512; k += 128) {
        float pv;
        if (k < 256) {
            int key = g_poolmax[g * 256 + k];
            pv = (key == INT_MIN) ? 0.f : funmap_f(key);
        } else {
            pv = g_poolsum[g * 256 + (k - 256)] / cnt;
        }
#pragma unroll
        for (int j = 0; j < 4; j++) a[j] = fmaf(pv, Wd[k * 4 + j], a[j]);
    }
#pragma unroll
    for (int j = 0; j < 4; j++) sh[j][tid] = a[j];
    __syncthreads();
    for (int off = 64; off >= 1; off >>= 1) {
        if (tid < off) {
#pragma unroll
            for (int j = 0; j < 4; j++) sh[j][tid] += sh[j][tid + off];
        }
        __syncthreads();
    }
    if (tid == 0) {
        float l[4];
#pragma unroll
        for (int j = 0; j < 4; j++) l[j] = sh[j][0] + bd[j];
        float m = fmaxf(fmaxf(l[0], l[1]), fmaxf(l[2], l[3]));
        float se = 0.f;
#pragma unroll
        for (int j = 0; j < 4; j++) se += expf(l[j] - m);
        float lse = m + logf(se);
#pragma unroll
        for (int j = 0; j < 4; j++) out[g * 4 + j] = l[j] - lse;
    }
}

// ---------------------------------------------------------------------------
// Host launcher
// ---------------------------------------------------------------------------
extern "C" void kernel_launch(void* const* d_in, const int* in_sizes, int n_in,
                              void* d_out, int out_size) {
    const float *x, *ew, *W[5], *b[5], *gm[4], *be[4], *Wd, *bd;
    const int *ei, *bi;

    bool setup_order = (in_sizes[2] > 1000000);
    if (setup_order) {
        x  = (const float*)d_in[0];
        ew = (const float*)d_in[1];
        ei = (const int*)  d_in[2];
        bi = (const int*)  d_in[3];
        int p = 4;
        for (int l = 0; l < 5; l++) {
            W[l] = (const float*)d_in[p++];
            b[l] = (const float*)d_in[p++];
            if (l < 4) { gm[l] = (const float*)d_in[p++]; be[l] = (const float*)d_in[p++]; }
        }
        Wd = (const float*)d_in[p++];
        bd = (const float*)d_in[p++];
    } else {
        x  = (const float*)d_in[0];
        ew = (const float*)d_in[1];
        int p = 2;
        for (int l = 0; l < 5; l++) {
            W[l] = (const float*)d_in[p++];
            b[l] = (const float*)d_in[p++];
            if (l < 4) { gm[l] = (const float*)d_in[p++]; be[l] = (const float*)d_in[p++]; }
        }
        Wd = (const float*)d_in[p++];
        bd = (const float*)d_in[p++];
        ei = (const int*)d_in[p++];
        bi = (const int*)d_in[p++];
    }

    const int n = in_sizes[0] / 128;
    const int E = in_sizes[1];
    const int G = out_size / 4;     // 64
    float* out = (float*)d_out;

    // side stream (created once; graph-capture forks/joins via events)
    static cudaStream_t s2 = nullptr;
    static cudaEvent_t evFork = nullptr, evJoin = nullptr;
    if (!s2) {
        cudaStreamCreateWithFlags(&s2, cudaStreamNonBlocking);
        cudaEventCreateWithFlags(&evFork, cudaEventDisableTiming);
        cudaEventCreateWithFlags(&evJoin, cudaEventDisableTiming);
    }

    // fork: layer-0 GEMM + pool setup run parallel to the CSR build
    cudaEventRecord(evFork, 0);
    cudaStreamWaitEvent(s2, evFork, 0);
    cheb_gemm0_k<<<(n + 127) / 128, 128, 0, s2>>>(x, W[0], n);
    pool_setup_k<<<(G * 256 + 255) / 256, 256, 0, s2>>>(bi, n, G);

    // main stream: packed deg/cnt, dinv, CSR build
    zero_init_k<<<(n + 255) / 256, 256>>>(n);
    edge_deg_k<<<(E + 255) / 256, 256>>>(ei, ew, E);
    rowbase_k<<<(n + 1023) / 1024, 1024>>>(n);
    edge_fill_k<<<(E + 255) / 256, 256>>>(ei, ew, E);

    // join
    cudaEventRecord(evJoin, s2);
    cudaStreamWaitEvent(0, evJoin, 0);

    // ---- Layer 0 (commuted; props at width 16, half state; stats fused) ----
    {
        dim3 blk(2, 128);
        int grd = (n + 127) / 128;
        prop_h_k<2><<<grd, blk>>>(n, 2, nullptr);   // T = C1 + 2 L C2  -> g_T1h
        prop_h_k<3><<<grd, blk>>>(n, 2, b[0]);      // H = sp(C0 - C2 + L T + b) + stats
    }
    {
        int total4 = n * 16 / 4;
        int agrid = (total4 + 255) / 256; if (agrid > 2048) agrid = 2048;
        bn_apply_h_k<<<agrid, 256>>>(total4, 16, gm[0], be[0], 0, n);
    }

    // ---- Layers 1-4 (all props on half state; stats fused in producers) ----
    for (int l = 1; l < 5; l++) {
        int gx = (n + 127) / 128;
        int fi8 = (l == 1) ? 2 : (l == 2) ? 4 : (l == 3) ? 8 : 16;
        dim3 blk(fi8, 256 / fi8);
        int grd = (n + blk.y - 1) / blk.y;
        prop_h_k<0><<<grd, blk>>>(n, fi8, nullptr);   // T1h = L Zh
        prop_h_k<1><<<grd, blk>>>(n, fi8, nullptr);   // T2h = L T1h

        switch (l) {
            case 1: cheb_gemm2_k< 16,  32, 4, 128, true ><<<(n + 63) / 64, 128>>>(W[1], b[1], n, 1); break;
            case 2: cheb_gemm2_k< 32,  64, 8, 128, true ><<<(n + 63) / 64, 128>>>(W[2], b[2], n, 2); break;
            case 3: cheb_mma_k< 64, 128, true,  false><<<dim3(gx, 2), 256>>>(W[3], b[3], n, 3, nullptr); break;
            case 4: cheb_mma_k<128, 256, false, true ><<<dim3(gx, 4), 256>>>(W[4], b[4], n, 4, bi); break;
        }

        if (l < 4) {
            const int FO = (l == 1) ? 32 : (l == 2) ? 64 : 128;
            int total4 = n * FO / 4;
            int agrid = (total4 + 255) / 256; if (agrid > 2048) agrid = 2048;
            bn_apply_h_k<<<agrid, 256>>>(total4, FO, gm[l], be[l], l, n);
        }
    }

    // ---- dense head (pooling fused into layer-4 mma) ----
    dense_k<<<G, 128>>>(Wd, bd, out);
}

// round 12
// speedup vs baseline: 1.0686x; 1.0050x over previous
#include <cuda_runtime.h>
#include <cuda_fp16.h>
#include <math.h>
#include <float.h>

// ---------------------------------------------------------------------------
// Problem constants (fixed by the dataset)
// ---------------------------------------------------------------------------
#define NMAX 50048
#define EMAX 1600000
#define GMAXC 64

typedef unsigned long long ull;

// ---------------------------------------------------------------------------
// Scratch (static device globals; no allocation at runtime)
// ---------------------------------------------------------------------------
__device__ ull   g_degcnt[NMAX];
__device__ float g_dinv[NMAX];
__device__ int   g_cnt[NMAX];
__device__ int   g_fill[NMAX];
__device__ int   g_rowstart[NMAX];
__device__ int   g_total;
__device__ unsigned int g_epack[EMAX];   // low16 = col, high16 = fp16 weight
__device__ float g_T1[NMAX * 16];      // layer-0 C1 (fp32, pointwise reads only)
__device__ float g_H [NMAX * 256];     // fp32 activations (pre-BN)
__device__ __half g_Zh [NMAX * 128];
__device__ __half g_T1h[NMAX * 128];
__device__ __half g_T2h[NMAX * 128];
__device__ float g_bnsum[1024];        // [4 layers][256]
__device__ float g_bnsq [1024];
__device__ int   g_poolmax[GMAXC * 256];
__device__ float g_poolsum[GMAXC * 256];
__device__ int   g_segstart[GMAXC + 1];

// ---------------------------------------------------------------------------
// Helpers
// ---------------------------------------------------------------------------
__device__ __forceinline__ float softplus_f(float x) {
    return fmaxf(x, 0.f) + log1pf(expf(-fabsf(x)));
}

__device__ __forceinline__ int fmap_f(float f) {
    int i = __float_as_int(f);
    return (i < 0) ? (i ^ 0x7FFFFFFF) : i;
}
__device__ __forceinline__ float funmap_f(int k) {
    return __int_as_float((k < 0) ? (k ^ 0x7FFFFFFF) : k);
}

__device__ __forceinline__ float unpack_w(unsigned int pk) {
    return __half2float(__ushort_as_half((unsigned short)(pk >> 16)));
}

// packed fp32x2 FMA (Blackwell): d = a*b + d per 32-bit lane
__device__ __forceinline__ void fma2(ull &d, ull a, ull b) {
    asm("fma.rn.f32x2 %0, %1, %2, %0;" : "+l"(d) : "l"(a), "l"(b));
}
__device__ __forceinline__ ull bc2(float a) {
    ull r; unsigned int u = __float_as_uint(a);
    asm("mov.b64 %0, {%1, %1};" : "=l"(r) : "r"(u));
    return r;
}
union F2U { ull u; float2 f; };
union H2I { __half2 h; int i; };

__device__ __forceinline__ unsigned int tf32_of(float x) {
    unsigned int u;
    asm("cvt.rna.tf32.f32 %0, %1;" : "=r"(u) : "f"(x));
    return u;
}

__device__ __forceinline__ void mma_tf32(
    float &c0, float &c1, float &c2, float &c3,
    unsigned int a0, unsigned int a1, unsigned int a2, unsigned int a3,
    unsigned int b0, unsigned int b1)
{
    asm volatile(
        "mma.sync.aligned.m16n8k8.row.col.f32.tf32.tf32.f32 "
        "{%0,%1,%2,%3}, {%4,%5,%6,%7}, {%8,%9}, {%0,%1,%2,%3};"
        : "+f"(c0), "+f"(c1), "+f"(c2), "+f"(c3)
        : "r"(a0), "r"(a1), "r"(a2), "r"(a3), "r"(b0), "r"(b1));
}

// ---------------------------------------------------------------------------
// Preprocessing
// ---------------------------------------------------------------------------
__global__ void zero_init_k(int n) {
    int i = blockIdx.x * blockDim.x + threadIdx.x;
    if (i < n) g_degcnt[i] = 0ull;
    if (i < 1024) { g_bnsum[i] = 0.f; g_bnsq[i] = 0.f; }
    if (i == 0) g_total = 0;
}

// one 64-bit atomic per edge: count in bits[40:], deg-sum as 24-bit fixed point
__global__ void edge_deg_k(const int* __restrict__ ei, const float* __restrict__ ew, int E) {
    int e = blockIdx.x * blockDim.x + threadIdx.x;
    if (e >= E) return;
    int r = ei[e];
    ull v = (1ull << 40) | (ull)__float2uint_rn(ew[e] * 16777216.f);
    atomicAdd(&g_degcnt[r], v);
}

// fused: unpack deg/cnt + dinv + per-block scan + one global atomic per block
// also preloads g_fill with the exclusive rowstart (edge_fill cursor)
__global__ void rowbase_k(int n) {
    __shared__ int wsum[32];
    __shared__ int blockbase;
    int tid = threadIdx.x, lane = tid & 31, wid = tid >> 5;
    int i = blockIdx.x * 1024 + tid;
    int v = 0;
    if (i < n) {
        ull dv = g_degcnt[i];
        v = (int)(dv >> 40);
        float d = (float)(dv & 0xFFFFFFFFFFull) * (1.f / 16777216.f);
        g_dinv[i] = (d > 0.f) ? rsqrtf(d) : 0.f;
        g_cnt[i] = v;
    }
    int x = v;
#pragma unroll
    for (int off = 1; off < 32; off <<= 1) {
        int t = __shfl_up_sync(0xffffffffu, x, off);
        if (lane >= off) x += t;
    }
    if (lane == 31) wsum[wid] = x;
    __syncthreads();
    if (wid == 0) {
        int y = wsum[lane];
#pragma unroll
        for (int off = 1; off < 32; off <<= 1) {
            int t = __shfl_up_sync(0xffffffffu, y, off);
            if (lane >= off) y += t;
        }
        wsum[lane] = y;
    }
    __syncthreads();
    if (tid == 0) blockbase = atomicAdd(&g_total, wsum[31]);
    __syncthreads();
    int pre = (wid > 0) ? wsum[wid - 1] : 0;
    if (i < n) {
        int rs = blockbase + pre + x - v;
        g_rowstart[i] = rs;
        g_fill[i] = rs;    // cursor for edge_fill
    }
}

__global__ void edge_fill_k(const int* __restrict__ ei, const float* __restrict__ ew, int E) {
    int e = blockIdx.x * blockDim.x + threadIdx.x;
    if (e >= E) return;
    int r = ei[e];
    int c = ei[E + e];
    int p = atomicAdd(&g_fill[r], 1);   // cursor preloaded with rowstart
    float nw = -ew[e] * g_dinv[r] * g_dinv[c];
    unsigned int hw = (unsigned int)__half_as_ushort(__float2half_rn(nw));
    g_epack[p] = (unsigned int)c | (hw << 16);
}

// ---------------------------------------------------------------------------
// Sparse propagation (half state, fp32 accumulate). Thread = (row, 8 features).
// 8-edge unrolled main loop with uint4 edge-pack loads (4 edges per 16B).
// MODE 0: g_Zh  -> g_T1h            (generic T1 = L Z)
// MODE 1: g_T1h -> g_T2h            (generic T2raw = L T1)
// MODE 2: gather g_Zh (=C2), out g_T1h = half(g_T1_f32 + 2*acc)       [layer 0]
// MODE 3: gather g_T1h (=T), out g_H = sp(g_H - toF(g_Zh) + acc + b)
//         + fused BN stats for layer 0                                 [layer 0]
// ---------------------------------------------------------------------------
template<int MODE>
__global__ void prop_h_k(int n, int fi8, const float* __restrict__ bias) {
    __shared__ float ssum[16], ssq[16];
    int flat = threadIdx.y * blockDim.x + threadIdx.x;
    if (MODE == 3) {
        if (flat < 16) { ssum[flat] = 0.f; ssq[flat] = 0.f; }
        __syncthreads();
    }
    int row = blockIdx.x * blockDim.y + threadIdx.y;
    if (row >= n) return;
    const int4* Zin = (const int4*)((MODE == 0 || MODE == 2) ? g_Zh : g_T1h);
    int xf = threadIdx.x;
    int s = g_rowstart[row];
    int e = s + g_cnt[row];
    float acc[8];
#pragma unroll
    for (int j = 0; j < 8; j++) acc[j] = 0.f;

    int i = s;
    // peel to 4-edge (16B) alignment
    for (; i < e && (i & 3); i++) {
        unsigned int pk = g_epack[i];
        int4 v = Zin[(pk & 0xFFFFu) * fi8 + xf];
        float w = unpack_w(pk);
        const __half2* h = (const __half2*)&v;
#pragma unroll
        for (int j = 0; j < 4; j++) {
            float2 f = __half22float2(h[j]);
            acc[2*j]   = fmaf(w, f.x, acc[2*j]);
            acc[2*j+1] = fmaf(w, f.y, acc[2*j+1]);
        }
    }
    // 8-edge unrolled: 2 x uint4 pack loads + 8 independent gathers
    for (; i + 8 <= e; i += 8) {
        uint4 pA = *(const uint4*)&g_epack[i];
        uint4 pB = *(const uint4*)&g_epack[i + 4];
        int4 v0 = Zin[(pA.x & 0xFFFFu) * fi8 + xf];
        int4 v1 = Zin[(pA.y & 0xFFFFu) * fi8 + xf];
        int4 v2 = Zin[(pA.z & 0xFFFFu) * fi8 + xf];
        int4 v3 = Zin[(pA.w & 0xFFFFu) * fi8 + xf];
        int4 v4 = Zin[(pB.x & 0xFFFFu) * fi8 + xf];
        int4 v5 = Zin[(pB.y & 0xFFFFu) * fi8 + xf];
        int4 v6 = Zin[(pB.z & 0xFFFFu) * fi8 + xf];
        int4 v7 = Zin[(pB.w & 0xFFFFu) * fi8 + xf];
        float w0 = unpack_w(pA.x), w1 = unpack_w(pA.y);
        float w2 = unpack_w(pA.z), w3 = unpack_w(pA.w);
        float w4 = unpack_w(pB.x), w5 = unpack_w(pB.y);
        float w6 = unpack_w(pB.z), w7 = unpack_w(pB.w);
        const __half2* h0 = (const __half2*)&v0;
        const __half2* h1 = (const __half2*)&v1;
        const __half2* h2 = (const __half2*)&v2;
        const __half2* h3 = (const __half2*)&v3;
        const __half2* h4 = (const __half2*)&v4;
        const __half2* h5 = (const __half2*)&v5;
        const __half2* h6 = (const __half2*)&v6;
        const __half2* h7 = (const __half2*)&v7;
#pragma unroll
        for (int j = 0; j < 4; j++) {
            float2 f0 = __half22float2(h0[j]);
            float2 f1 = __half22float2(h1[j]);
            float2 f2 = __half22float2(h2[j]);
            float2 f3 = __half22float2(h3[j]);
            acc[2*j]   = fmaf(w0, f0.x, acc[2*j]);   acc[2*j+1] = fmaf(w0, f0.y, acc[2*j+1]);
            acc[2*j]   = fmaf(w1, f1.x, acc[2*j]);   acc[2*j+1] = fmaf(w1, f1.y, acc[2*j+1]);
            acc[2*j]   = fmaf(w2, f2.x, acc[2*j]);   acc[2*j+1] = fmaf(w2, f2.y, acc[2*j+1]);
            acc[2*j]   = fmaf(w3, f3.x, acc[2*j]);   acc[2*j+1] = fmaf(w3, f3.y, acc[2*j+1]);
            float2 f4 = __half22float2(h4[j]);
            float2 f5 = __half22float2(h5[j]);
            float2 f6 = __half22float2(h6[j]);
            float2 f7 = __half22float2(h7[j]);
            acc[2*j]   = fmaf(w4, f4.x, acc[2*j]);   acc[2*j+1] = fmaf(w4, f4.y, acc[2*j+1]);
            acc[2*j]   = fmaf(w5, f5.x, acc[2*j]);   acc[2*j+1] = fmaf(w5, f5.y, acc[2*j+1]);
            acc[2*j]   = fmaf(w6, f6.x, acc[2*j]);   acc[2*j+1] = fmaf(w6, f6.y, acc[2*j+1]);
            acc[2*j]   = fmaf(w7, f7.x, acc[2*j]);   acc[2*j+1] = fmaf(w7, f7.y, acc[2*j+1]);
        }
    }
    // 4-edge tail
    for (; i + 4 <= e; i += 4) {
        uint4 pA = *(const uint4*)&g_epack[i];
        int4 v0 = Zin[(pA.x & 0xFFFFu) * fi8 + xf];
        int4 v1 = Zin[(pA.y & 0xFFFFu) * fi8 + xf];
        int4 v2 = Zin[(pA.z & 0xFFFFu) * fi8 + xf];
        int4 v3 = Zin[(pA.w & 0xFFFFu) * fi8 + xf];
        float w0 = unpack_w(pA.x), w1 = unpack_w(pA.y);
        float w2 = unpack_w(pA.z), w3 = unpack_w(pA.w);
        const __half2* h0 = (const __half2*)&v0;
        const __half2* h1 = (const __half2*)&v1;
        const __half2* h2 = (const __half2*)&v2;
        const __half2* h3 = (const __half2*)&v3;
#pragma unroll
        for (int j = 0; j < 4; j++) {
            float2 f0 = __half22float2(h0[j]);
            float2 f1 = __half22float2(h1[j]);
            float2 f2 = __half22float2(h2[j]);
            float2 f3 = __half22float2(h3[j]);
            acc[2*j]   = fmaf(w0, f0.x, acc[2*j]);   acc[2*j+1] = fmaf(w0, f0.y, acc[2*j+1]);
            acc[2*j]   = fmaf(w1, f1.x, acc[2*j]);   acc[2*j+1] = fmaf(w1, f1.y, acc[2*j+1]);
            acc[2*j]   = fmaf(w2, f2.x, acc[2*j]);   acc[2*j+1] = fmaf(w2, f2.y, acc[2*j+1]);
            acc[2*j]   = fmaf(w3, f3.x, acc[2*j]);   acc[2*j+1] = fmaf(w3, f3.y, acc[2*j+1]);
        }
    }
    for (; i < e; i++) {
        unsigned int pk = g_epack[i];
        int4 v = Zin[(pk & 0xFFFFu) * fi8 + xf];
        float w = unpack_w(pk);
        const __half2* h = (const __half2*)&v;
#pragma unroll
        for (int j = 0; j < 4; j++) {
            float2 f = __half22float2(h[j]);
            acc[2*j]   = fmaf(w, f.x, acc[2*j]);
            acc[2*j+1] = fmaf(w, f.y, acc[2*j+1]);
        }
    }

    int idx = row * fi8 + xf;
    if (MODE == 0 || MODE == 1) {
        int4 o; __half2* op = (__half2*)&o;
#pragma unroll
        for (int j = 0; j < 4; j++) op[j] = __floats2half2_rn(acc[2*j], acc[2*j+1]);
        ((int4*)(MODE == 0 ? g_T1h : g_T2h))[idx] = o;
    } else if (MODE == 2) {
        // T = C1 + 2 * acc   (C1 fp32 pointwise)
        int fbase = row * (fi8 * 2) + xf * 2;
        float4 c1a = ((const float4*)g_T1)[fbase];
        float4 c1b = ((const float4*)g_T1)[fbase + 1];
        float cv[8] = {c1a.x, c1a.y, c1a.z, c1a.w, c1b.x, c1b.y, c1b.z, c1b.w};
        int4 o; __half2* op = (__half2*)&o;
#pragma unroll
        for (int j = 0; j < 4; j++)
            op[j] = __floats2half2_rn(cv[2*j] + 2.f*acc[2*j], cv[2*j+1] + 2.f*acc[2*j+1]);
        ((int4*)g_T1h)[idx] = o;
    } else {
        // H = softplus(C0 - C2 + acc + b), fused layer-0 BN stats
        int fbase = row * (fi8 * 2) + xf * 2;
        float4 h0 = ((const float4*)g_H)[fbase];
        float4 h1 = ((const float4*)g_H)[fbase + 1];
        float hv[8] = {h0.x, h0.y, h0.z, h0.w, h1.x, h1.y, h1.z, h1.w};
        int4 vz = ((const int4*)g_Zh)[idx];
        const __half2* hz = (const __half2*)&vz;
        float4 b0 = ((const float4*)bias)[xf * 2];
        float4 b1 = ((const float4*)bias)[xf * 2 + 1];
        float bv[8] = {b0.x, b0.y, b0.z, b0.w, b1.x, b1.y, b1.z, b1.w};
        float ov[8];
#pragma unroll
        for (int j = 0; j < 4; j++) {
            float2 fz = __half22float2(hz[j]);
            ov[2*j]   = softplus_f(hv[2*j]   - fz.x + acc[2*j]   + bv[2*j]);
            ov[2*j+1] = softplus_f(hv[2*j+1] - fz.y + acc[2*j+1] + bv[2*j+1]);
        }
        ((float4*)g_H)[fbase]     = make_float4(ov[0], ov[1], ov[2], ov[3]);
        ((float4*)g_H)[fbase + 1] = make_float4(ov[4], ov[5], ov[6], ov[7]);
#pragma unroll
        for (int j = 0; j < 8; j++) {
            atomicAdd(&ssum[xf * 8 + j], ov[j]);
            atomicAdd(&ssq [xf * 8 + j], ov[j] * ov[j]);
        }
        __syncthreads();
        if (flat < 16) {
            atomicAdd(&g_bnsum[flat], ssum[flat]);
            atomicAdd(&g_bnsq [flat], ssq[flat]);
        }
    }
}

// ---------------------------------------------------------------------------
// Layer-0 commuted GEMM: C0 = x@W0 -> g_H (fp32), C1 = x@W1 -> g_T1 (fp32),
// C2 = x@W2 -> g_Zh (half).  FI=128, per-mat FO=16.
// ---------------------------------------------------------------------------
__global__ void __launch_bounds__(128) cheb_gemm0_k(
    const float* __restrict__ x, const float* __restrict__ W, int n)
{
    constexpr int CG = 4, RPI = 32, RM = 4, BM = RPI * RM;   // BM = 128
    const int cg = threadIdx.x % CG, r0 = threadIdx.x / CG;
    const int rowbase = blockIdx.x * BM;
    const ulonglong2* Wp = (const ulonglong2*)W;   // [3][128][4] of ull2
    const float4* X4 = (const float4*)x;

    ull acc0[RM][2], acc1[RM][2], acc2[RM][2];
    int rows[RM]; bool vld[RM];
#pragma unroll
    for (int r = 0; r < RM; r++) {
        acc0[r][0] = acc0[r][1] = 0ull;
        acc1[r][0] = acc1[r][1] = 0ull;
        acc2[r][0] = acc2[r][1] = 0ull;
        rows[r] = rowbase + r0 + r * RPI;
        vld[r]  = rows[r] < n;
    }

    for (int k0 = 0; k0 < 128; k0 += 4) {
        ulonglong2 w0[4], w1[4], w2[4];
#pragma unroll
        for (int kk = 0; kk < 4; kk++) {
            int wi = (k0 + kk) * CG + cg;
            w0[kk] = Wp[wi];
            w1[kk] = Wp[512 + wi];
            w2[kk] = Wp[1024 + wi];
        }
#pragma unroll
        for (int r = 0; r < RM; r++) {
            float4 z4 = make_float4(0.f, 0.f, 0.f, 0.f);
            if (vld[r]) z4 = X4[rows[r] * 32 + (k0 >> 2)];
            float zz[4] = {z4.x, z4.y, z4.z, z4.w};
#pragma unroll
            for (int kk = 0; kk < 4; kk++) {
                ull a2 = bc2(zz[kk]);
                fma2(acc0[r][0], a2, w0[kk].x); fma2(acc0[r][1], a2, w0[kk].y);
                fma2(acc1[r][0], a2, w1[kk].x); fma2(acc1[r][1], a2, w1[kk].y);
                fma2(acc2[r][0], a2, w2[kk].x); fma2(acc2[r][1], a2, w2[kk].y);
            }
        }
    }

#pragma unroll
    for (int r = 0; r < RM; r++) {
        if (!vld[r]) continue;
        int off = rows[r] * CG + cg;
        F2U l, h;
        l.u = acc0[r][0]; h.u = acc0[r][1];
        ((float4*)g_H )[off] = make_float4(l.f.x, l.f.y, h.f.x, h.f.y);
        l.u = acc1[r][0]; h.u = acc1[r][1];
        ((float4*)g_T1)[off] = make_float4(l.f.x, l.f.y, h.f.x, h.f.y);
        l.u = acc2[r][0]; h.u = acc2[r][1];
        H2I p0, p1;
        p0.h = __floats2half2_rn(l.f.x, l.f.y);
        p1.h = __floats2half2_rn(h.f.x, h.f.y);
        ((int2*)g_Zh)[off] = make_int2(p0.i, p1.i);
    }
}

// ---------------------------------------------------------------------------
// SIMT Chebyshev combine GEMM (layers 1-2), f32x2 packed, half inputs,
// fused BN stats:  H = Z W0 + T1 W1 + (2 T2raw - Z) W2 + b  (+ softplus)
// ---------------------------------------------------------------------------
template<int FI, int FO, int RM, int THREADS, bool ACT>
__global__ void __launch_bounds__(THREADS) cheb_gemm2_k(
    const float* __restrict__ W, const float* __restrict__ b, int n, int lidx)
{
    constexpr int CG = FO / 4;
    constexpr int RPI = THREADS / CG;
    constexpr int BM = RPI * RM;
    __shared__ float ssum[FO], ssq[FO];
    const int tid = threadIdx.x;
    const int cg = tid % CG, r0 = tid / CG;
    const int rowbase = blockIdx.x * BM;
    if (tid < FO) { ssum[tid] = 0.f; ssq[tid] = 0.f; }
    __syncthreads();

    const ulonglong2* Wp = (const ulonglong2*)W;   // [3][FI][CG] of ull2
    const int2* Zh = (const int2*)g_Zh;
    const int2* Ah = (const int2*)g_T1h;
    const int2* Ph = (const int2*)g_T2h;

    ulonglong2 bb = ((const ulonglong2*)b)[cg];
    ull acc[RM][2];
    int rows[RM]; bool vld[RM];
#pragma unroll
    for (int r = 0; r < RM; r++) {
        acc[r][0] = bb.x; acc[r][1] = bb.y;
        rows[r] = rowbase + r0 + r * RPI;
        vld[r]  = rows[r] < n;
    }

    for (int k0 = 0; k0 < FI; k0 += 4) {
        ulonglong2 w0[4], w1[4], w2[4];
#pragma unroll
        for (int kk = 0; kk < 4; kk++) {
            int wi = (k0 + kk) * CG + cg;
            w0[kk] = Wp[wi];
            w1[kk] = Wp[FI * CG + wi];
            w2[kk] = Wp[2 * FI * CG + wi];
        }
#pragma unroll
        for (int r = 0; r < RM; r++) {
            float zz[4] = {0.f, 0.f, 0.f, 0.f};
            float tt[4] = {0.f, 0.f, 0.f, 0.f};
            float uu[4] = {0.f, 0.f, 0.f, 0.f};
            if (vld[r]) {
                int off = rows[r] * (FI / 4) + (k0 >> 2);
                int2 vz = Zh[off], va = Ah[off], vp = Ph[off];
                H2I u;
                u.i = vz.x; float2 z0 = __half22float2(u.h);
                u.i = vz.y; float2 z1 = __half22float2(u.h);
                u.i = va.x; float2 a0 = __half22float2(u.h);
                u.i = va.y; float2 a1 = __half22float2(u.h);
                u.i = vp.x; float2 p0 = __half22float2(u.h);
                u.i = vp.y; float2 p1 = __half22float2(u.h);
                zz[0] = z0.x; zz[1] = z0.y; zz[2] = z1.x; zz[3] = z1.y;
                tt[0] = a0.x; tt[1] = a0.y; tt[2] = a1.x; tt[3] = a1.y;
                uu[0] = 2.f*p0.x - z0.x; uu[1] = 2.f*p0.y - z0.y;
                uu[2] = 2.f*p1.x - z1.x; uu[3] = 2.f*p1.y - z1.y;
            }
#pragma unroll
            for (int kk = 0; kk < 4; kk++) {
                ull a2 = bc2(zz[kk]);
                fma2(acc[r][0], a2, w0[kk].x); fma2(acc[r][1], a2, w0[kk].y);
                ull t2 = bc2(tt[kk]);
                fma2(acc[r][0], t2, w1[kk].x); fma2(acc[r][1], t2, w1[kk].y);
                ull u2 = bc2(uu[kk]);
                fma2(acc[r][0], u2, w2[kk].x); fma2(acc[r][1], u2, w2[kk].y);
            }
        }
    }

    float ls[4] = {0.f, 0.f, 0.f, 0.f}, lq[4] = {0.f, 0.f, 0.f, 0.f};
#pragma unroll
    for (int r = 0; r < RM; r++) {
        if (!vld[r]) continue;
        F2U l, h; l.u = acc[r][0]; h.u = acc[r][1];
        float4 o = make_float4(l.f.x, l.f.y, h.f.x, h.f.y);
        if (ACT) {
            o.x = softplus_f(o.x); o.y = softplus_f(o.y);
            o.z = softplus_f(o.z); o.w = softplus_f(o.w);
        }
        ((float4*)g_H)[rows[r] * CG + cg] = o;
        ls[0] += o.x; ls[1] += o.y; ls[2] += o.z; ls[3] += o.w;
        lq[0] = fmaf(o.x, o.x, lq[0]); lq[1] = fmaf(o.y, o.y, lq[1]);
        lq[2] = fmaf(o.z, o.z, lq[2]); lq[3] = fmaf(o.w, o.w, lq[3]);
    }
#pragma unroll
    for (int j = 0; j < 4; j++) {
        atomicAdd(&ssum[cg * 4 + j], ls[j]);
        atomicAdd(&ssq [cg * 4 + j], lq[j]);
    }
    __syncthreads();
    if (tid < FO) {
        atomicAdd(&g_bnsum[lidx * 256 + tid], ssum[tid]);
        atomicAdd(&g_bnsq [lidx * 256 + tid], ssq[tid]);
    }
}

// ---------------------------------------------------------------------------
// Tensor-core (tf32 mma.sync) Chebyshev combine GEMM, layers 3-4.
// A operands from half buffers. Block tile 128x64, 8 warps (4x2), m16n8k8.
// ACT (layer 3): softplus + fused BN stats, writes g_H.
// POOL (layer 4): NO g_H write — per-block smem pooling (max/sum per graph),
//                 merged into g_poolmax/g_poolsum with global atomics.
// ---------------------------------------------------------------------------
template<int FI, int FO, bool ACT, bool POOL>
__global__ void __launch_bounds__(256) cheb_mma_k(
    const float* __restrict__ W, const float* __restrict__ bias, int n, int lidx,
    const int* __restrict__ bi)
{
    constexpr int BM = 128, BN = 64, KC = 16;
    constexpr int APAD = 136;
    constexpr int BPAD = 72;
    constexpr int PSLOTS = 8;
    __shared__ unsigned int As[KC][APAD];
    __shared__ unsigned int Bs[KC][BPAD];
    __shared__ float ssum[BN], ssq[BN];
    __shared__ int   pmax[POOL ? PSLOTS * BN : 1];
    __shared__ float psum[POOL ? PSLOTS * BN : 1];

    const int tid  = threadIdx.x;
    const int lane = tid & 31, wid = tid >> 5;
    const int wm = wid & 3, wn = wid >> 2;
    const int g = lane >> 2, tig = lane & 3;
    const int row0 = blockIdx.x * BM;
    const int n0   = blockIdx.y * BN;

    if (ACT) {
        if (tid < BN) { ssum[tid] = 0.f; ssq[tid] = 0.f; }
    }

    float c[2][4][4];
#pragma unroll
    for (int mt = 0; mt < 2; mt++)
#pragma unroll
        for (int nt = 0; nt < 4; nt++)
#pragma unroll
            for (int j = 0; j < 4; j++) c[mt][nt][j] = 0.f;

    const int lrow = tid & 127;
    const int lcol = (tid >> 7) * 8;
    const int grow = row0 + lrow;
    const bool lvalid = grow < n;
    const int bk = tid >> 4;
    const int bn = (tid & 15) * 4;

    for (int seg = 0; seg < 3; seg++) {
        const float* Wseg = W + seg * FI * FO;
        for (int kb = 0; kb < FI; kb += KC) {
            float f[8];
#pragma unroll
            for (int j = 0; j < 8; j++) f[j] = 0.f;
            if (lvalid) {
                int base = (grow * FI + kb + lcol) >> 3;
                if (seg == 0) {
                    int4 v = ((const int4*)g_Zh)[base];
                    const __half2* hp = (const __half2*)&v;
#pragma unroll
                    for (int j = 0; j < 4; j++) {
                        float2 ff = __half22float2(hp[j]);
                        f[2*j] = ff.x; f[2*j+1] = ff.y;
                    }
                } else if (seg == 1) {
                    int4 v = ((const int4*)g_T1h)[base];
                    const __half2* hp = (const __half2*)&v;
#pragma unroll
                    for (int j = 0; j < 4; j++) {
                        float2 ff = __half22float2(hp[j]);
                        f[2*j] = ff.x; f[2*j+1] = ff.y;
                    }
                } else {
                    int4 vp = ((const int4*)g_T2h)[base];
                    int4 vz = ((const int4*)g_Zh)[base];
                    const __half2* hp = (const __half2*)&vp;
                    const __half2* hz = (const __half2*)&vz;
#pragma unroll
                    for (int j = 0; j < 4; j++) {
                        float2 fp = __half22float2(hp[j]);
                        float2 fz = __half22float2(hz[j]);
                        f[2*j]   = 2.f*fp.x - fz.x;
                        f[2*j+1] = 2.f*fp.y - fz.y;
                    }
                }
            }
#pragma unroll
            for (int j = 0; j < 8; j++) As[lcol + j][lrow] = tf32_of(f[j]);
            {
                float4 w4 = *(const float4*)(Wseg + (kb + bk) * FO + n0 + bn);
                Bs[bk][bn + 0] = tf32_of(w4.x);
                Bs[bk][bn + 1] = tf32_of(w4.y);
                Bs[bk][bn + 2] = tf32_of(w4.z);
                Bs[bk][bn + 3] = tf32_of(w4.w);
            }
            __syncthreads();
#pragma unroll
            for (int k8 = 0; k8 < KC; k8 += 8) {
                unsigned int af[2][4];
#pragma unroll
                for (int mt = 0; mt < 2; mt++) {
                    int r = wm * 32 + mt * 16 + g;
                    af[mt][0] = As[k8 + tig    ][r];
                    af[mt][1] = As[k8 + tig    ][r + 8];
                    af[mt][2] = As[k8 + tig + 4][r];
                    af[mt][3] = As[k8 + tig + 4][r + 8];
                }
                unsigned int bf[4][2];
#pragma unroll
                for (int nt = 0; nt < 4; nt++) {
                    int cc = wn * 32 + nt * 8 + g;
                    bf[nt][0] = Bs[k8 + tig    ][cc];
                    bf[nt][1] = Bs[k8 + tig + 4][cc];
                }
#pragma unroll
                for (int mt = 0; mt < 2; mt++)
#pragma unroll
                    for (int nt = 0; nt < 4; nt++)
                        mma_tf32(c[mt][nt][0], c[mt][nt][1], c[mt][nt][2], c[mt][nt][3],
                                 af[mt][0], af[mt][1], af[mt][2], af[mt][3],
                                 bf[nt][0], bf[nt][1]);
            }
            __syncthreads();
        }
    }

    if (!POOL) {
        // ---- layer-3 epilogue: softplus + H write + fused BN stats ----
        float ls[4][2], lq[4][2];
        if (ACT) {
#pragma unroll
            for (int nt = 0; nt < 4; nt++) {
                ls[nt][0] = ls[nt][1] = 0.f;
                lq[nt][0] = lq[nt][1] = 0.f;
            }
        }
#pragma unroll
        for (int mt = 0; mt < 2; mt++) {
            int r_lo = row0 + wm * 32 + mt * 16 + g;
            int r_hi = r_lo + 8;
#pragma unroll
            for (int nt = 0; nt < 4; nt++) {
                int col = n0 + wn * 32 + nt * 8 + 2 * tig;
                float b0 = bias[col], b1 = bias[col + 1];
                float o0 = c[mt][nt][0] + b0, o1 = c[mt][nt][1] + b1;
                float o2 = c[mt][nt][2] + b0, o3 = c[mt][nt][3] + b1;
                if (ACT) {
                    o0 = softplus_f(o0); o1 = softplus_f(o1);
                    o2 = softplus_f(o2); o3 = softplus_f(o3);
                }
                if (r_lo < n) {
                    *(float2*)&g_H[r_lo * FO + col] = make_float2(o0, o1);
                    if (ACT) {
                        ls[nt][0] += o0; ls[nt][1] += o1;
                        lq[nt][0] = fmaf(o0, o0, lq[nt][0]);
                        lq[nt][1] = fmaf(o1, o1, lq[nt][1]);
                    }
                }
                if (r_hi < n) {
                    *(float2*)&g_H[r_hi * FO + col] = make_float2(o2, o3);
                    if (ACT) {
                        ls[nt][0] += o2; ls[nt][1] += o3;
                        lq[nt][0] = fmaf(o2, o2, lq[nt][0]);
                        lq[nt][1] = fmaf(o3, o3, lq[nt][1]);
                    }
                }
            }
        }
        if (ACT) {
            __syncthreads();
#pragma unroll
            for (int nt = 0; nt < 4; nt++) {
                int lc = wn * 32 + nt * 8 + 2 * tig;
                atomicAdd(&ssum[lc],     ls[nt][0]);
                atomicAdd(&ssum[lc + 1], ls[nt][1]);
                atomicAdd(&ssq [lc],     lq[nt][0]);
                atomicAdd(&ssq [lc + 1], lq[nt][1]);
            }
            __syncthreads();
            if (tid < BN) {
                atomicAdd(&g_bnsum[lidx * 256 + n0 + tid], ssum[tid]);
                atomicAdd(&g_bnsq [lidx * 256 + n0 + tid], ssq[tid]);
            }
        }
    } else {
        // ---- layer-4 epilogue: fused graph pooling (no H write) ----
        for (int i = tid; i < PSLOTS * BN; i += 256) { pmax[i] = INT_MIN; psum[i] = 0.f; }
        __syncthreads();
        const int gbase = bi[(row0 < n) ? row0 : (n - 1)];
        float vmax[8], vsum[8];
        int cur = -1;
#pragma unroll
        for (int k = 0; k < 4; k++) {
            int mt = k >> 1;
            int hi = k & 1;
            int r = row0 + wm * 32 + mt * 16 + g + (hi ? 8 : 0);
            if (r >= n) continue;
            int sl = bi[r] - gbase;
            if (sl != cur) {
                if (cur >= 0) {
#pragma unroll
                    for (int nt = 0; nt < 4; nt++) {
                        int lc = wn * 32 + nt * 8 + 2 * tig;
                        atomicMax(&pmax[cur * BN + lc],     fmap_f(vmax[2*nt]));
                        atomicMax(&pmax[cur * BN + lc + 1], fmap_f(vmax[2*nt+1]));
                        atomicAdd(&psum[cur * BN + lc],     vsum[2*nt]);
                        atomicAdd(&psum[cur * BN + lc + 1], vsum[2*nt+1]);
                    }
                }
                cur = sl;
#pragma unroll
                for (int j = 0; j < 8; j++) { vmax[j] = -FLT_MAX; vsum[j] = 0.f; }
            }
#pragma unroll
            for (int nt = 0; nt < 4; nt++) {
                int col = n0 + wn * 32 + nt * 8 + 2 * tig;
                float b0 = bias[col], b1 = bias[col + 1];
                float o0 = c[mt][nt][hi ? 2 : 0] + b0;
                float o1 = c[mt][nt][hi ? 3 : 1] + b1;
                if (cur < PSLOTS) {
                    vmax[2*nt]   = fmaxf(vmax[2*nt],   o0);
                    vmax[2*nt+1] = fmaxf(vmax[2*nt+1], o1);
                    vsum[2*nt]   += o0;
                    vsum[2*nt+1] += o1;
                } else {
                    int gg = bi[r];
                    atomicMax(&g_poolmax[gg * 256 + col],     fmap_f(o0));
                    atomicMax(&g_poolmax[gg * 256 + col + 1], fmap_f(o1));
                    atomicAdd(&g_poolsum[gg * 256 + col],     o0);
                    atomicAdd(&g_poolsum[gg * 256 + col + 1], o1);
                }
            }
        }
        if (cur >= 0 && cur < PSLOTS) {
#pragma unroll
            for (int nt = 0; nt < 4; nt++) {
                int lc = wn * 32 + nt * 8 + 2 * tig;
                atomicMax(&pmax[cur * BN + lc],     fmap_f(vmax[2*nt]));
                atomicMax(&pmax[cur * BN + lc + 1], fmap_f(vmax[2*nt+1]));
                atomicAdd(&psum[cur * BN + lc],     vsum[2*nt]);
                atomicAdd(&psum[cur * BN + lc + 1], vsum[2*nt+1]);
            }
        }
        __syncthreads();
        for (int i = tid; i < PSLOTS * BN; i += 256) {
            int sl = i / BN, cidx = i % BN;
            int mv = pmax[i];
            if (mv != INT_MIN) {
                atomicMax(&g_poolmax[(gbase + sl) * 256 + n0 + cidx], mv);
                atomicAdd(&g_poolsum[(gbase + sl) * 256 + n0 + cidx], psum[i]);
            }
        }
    }
}

// ---------------------------------------------------------------------------
// BN finalize+apply (stats already accumulated by producer kernels)
// ---------------------------------------------------------------------------
__global__ void bn_apply_h_k(int total4, int fo,
                             const float* __restrict__ gma,
                             const float* __restrict__ beta, int l, int n) {
    __shared__ float s_sc[256], s_sh[256];
    int tid = threadIdx.x;
    if (tid < fo) {
        float inv_n = 1.f / (float)n;
        float m = g_bnsum[l * 256 + tid] * inv_n;
        float v = g_bnsq[l * 256 + tid] * inv_n - m * m;
        float sc = gma[tid] * rsqrtf(fmaxf(v, 0.f) + 1e-5f);
        s_sc[tid] = sc;
        s_sh[tid] = beta[tid] - m * sc;
    }
    __syncthreads();
    int fo4 = fo >> 2;
    for (int i = blockIdx.x * blockDim.x + tid; i < total4;
         i += gridDim.x * blockDim.x) {
        float4 h = ((const float4*)g_H)[i];
        int f = (i % fo4) * 4;
        H2I a, b;
        a.h = __floats2half2_rn(fmaf(h.x, s_sc[f],     s_sh[f]),
                                fmaf(h.y, s_sc[f + 1], s_sh[f + 1]));
        b.h = __floats2half2_rn(fmaf(h.z, s_sc[f + 2], s_sh[f + 2]),
                                fmaf(h.w, s_sc[f + 3], s_sh[f + 3]));
        ((int2*)g_Zh)[i] = make_int2(a.i, b.i);
    }
}

// ---------------------------------------------------------------------------
// Pool init + segment bounds; dense head
// ---------------------------------------------------------------------------
__global__ void pool_setup_k(const int* __restrict__ batch, int n, int G) {
    int i = blockIdx.x * blockDim.x + threadIdx.x;
    if (i < G * 256) { g_poolmax[i] = INT_MIN; g_poolsum[i] = 0.f; }
    if (i <= G) {
        if (i == G) { g_segstart[G] = n; }
        else {
            int lo = 0, hi = n;
            while (lo < hi) {
                int mid = (lo + hi) >> 1;
                if (batch[mid] < i) lo = mid + 1; else hi = mid;
            }
            g_segstart[i] = lo;
        }
    }
}

__global__ void dense_k(const float* __restrict__ Wd, const float* __restrict__ bd,
                        float* __restrict__ out) {
    __shared__ float sh[4][128];
    int g = blockIdx.x, tid = threadIdx.x;
    int s = g_segstart[g], e = g_segstart[g + 1];
    float cnt = fmaxf((float)(e - s), 1.f);
    float a[4] = {0.f, 0.f, 0.f, 0.f};
    for (int k = tid; k < 512; k += 128) {
        float pv;
        if (k < 256) {
            int key = g_poolmax[g * 256 + k];
            pv = (key == INT_MIN) ? 0.f : funmap_f(key);
        } else {
            pv = g_poolsum[g * 256 + (k - 256)] / cnt;
        }
#pragma unroll
        for (int j = 0; j < 4; j++) a[j] = fmaf(pv, Wd[k * 4 + j], a[j]);
    }
#pragma unroll
    for (int j = 0; j < 4; j++) sh[j][tid] = a[j];
    __syncthreads();
    for (int off = 64; off >= 1; off >>= 1) {
        if (tid < off) {
#pragma unroll
            for (int j = 0; j < 4; j++) sh[j][tid] += sh[j][tid + off];
        }
        __syncthreads();
    }
    if (tid == 0) {
        float l[4];
#pragma unroll
        for (int j = 0; j < 4; j++) l[j] = sh[j][0] + bd[j];
        float m = fmaxf(fmaxf(l[0], l[1]), fmaxf(l[2], l[3]));
        float se = 0.f;
#pragma unroll
        for (int j = 0; j < 4; j++) se += expf(l[j] - m);
        float lse = m + logf(se);
#pragma unroll
        for (int j = 0; j < 4; j++) out[g * 4 + j] = l[j] - lse;
    }
}

// ---------------------------------------------------------------------------
// Host launcher
// ---------------------------------------------------------------------------
extern "C" void kernel_launch(void* const* d_in, const int* in_sizes, int n_in,
                              void* d_out, int out_size) {
    const float *x, *ew, *W[5], *b[5], *gm[4], *be[4], *Wd, *bd;
    const int *ei, *bi;

    bool setup_order = (in_sizes[2] > 1000000);
    if (setup_order) {
        x  = (const float*)d_in[0];
        ew = (const float*)d_in[1];
        ei = (const int*)  d_in[2];
        bi = (const int*)  d_in[3];
        int p = 4;
        for (int l = 0; l < 5; l++) {
            W[l] = (const float*)d_in[p++];
            b[l] = (const float*)d_in[p++];
            if (l < 4) { gm[l] = (const float*)d_in[p++]; be[l] = (const float*)d_in[p++]; }
        }
        Wd = (const float*)d_in[p++];
        bd = (const float*)d_in[p++];
    } else {
        x  = (const float*)d_in[0];
        ew = (const float*)d_in[1];
        int p = 2;
        for (int l = 0; l < 5; l++) {
            W[l] = (const float*)d_in[p++];
            b[l] = (const float*)d_in[p++];
            if (l < 4) { gm[l] = (const float*)d_in[p++]; be[l] = (const float*)d_in[p++]; }
        }
        Wd = (const float*)d_in[p++];
        bd = (const float*)d_in[p++];
        ei = (const int*)d_in[p++];
        bi = (const int*)d_in[p++];
    }

    const int n = in_sizes[0] / 128;
    const int E = in_sizes[1];
    const int G = out_size / 4;     // 64
    float* out = (float*)d_out;

    // side stream (created once; graph-capture forks/joins via events)
    static cudaStream_t s2 = nullptr;
    static cudaEvent_t evFork = nullptr, evJoin = nullptr;
    if (!s2) {
        cudaStreamCreateWithFlags(&s2, cudaStreamNonBlocking);
        cudaEventCreateWithFlags(&evFork, cudaEventDisableTiming);
        cudaEventCreateWithFlags(&evJoin, cudaEventDisableTiming);
    }

    // fork: layer-0 GEMM + pool setup run parallel to the CSR build
    cudaEventRecord(evFork, 0);
    cudaStreamWaitEvent(s2, evFork, 0);
    cheb_gemm0_k<<<(n + 127) / 128, 128, 0, s2>>>(x, W[0], n);
    pool_setup_k<<<(G * 256 + 255) / 256, 256, 0, s2>>>(bi, n, G);

    // main stream: packed deg/cnt, dinv, CSR build
    zero_init_k<<<(n + 255) / 256, 256>>>(n);
    edge_deg_k<<<(E + 255) / 256, 256>>>(ei, ew, E);
    rowbase_k<<<(n + 1023) / 1024, 1024>>>(n);
    edge_fill_k<<<(E + 255) / 256, 256>>>(ei, ew, E);

    // join
    cudaEventRecord(evJoin, s2);
    cudaStreamWaitEvent(0, evJoin, 0);

    // ---- Layer 0 (commuted; props at width 16, half state; stats fused) ----
    {
        dim3 blk(2, 128);
        int grd = (n + 127) / 128;
        prop_h_k<2><<<grd, blk>>>(n, 2, nullptr);   // T = C1 + 2 L C2  -> g_T1h
        prop_h_k<3><<<grd, blk>>>(n, 2, b[0]);      // H = sp(C0 - C2 + L T + b) + stats
    }
    {
        int total4 = n * 16 / 4;
        int agrid = (total4 + 255) / 256; if (agrid > 2048) agrid = 2048;
        bn_apply_h_k<<<agrid, 256>>>(total4, 16, gm[0], be[0], 0, n);
    }

    // ---- Layers 1-4 (all props on half state; stats fused in producers) ----
    for (int l = 1; l < 5; l++) {
        int gx = (n + 127) / 128;
        int fi8 = (l == 1) ? 2 : (l == 2) ? 4 : (l == 3) ? 8 : 16;
        dim3 blk(fi8, 256 / fi8);
        int grd = (n + blk.y - 1) / blk.y;
        prop_h_k<0><<<grd, blk>>>(n, fi8, nullptr);   // T1h = L Zh
        prop_h_k<1><<<grd, blk>>>(n, fi8, nullptr);   // T2h = L T1h

        switch (l) {
            case 1: cheb_gemm2_k< 16,  32, 4, 128, true ><<<(n + 63) / 64, 128>>>(W[1], b[1], n, 1); break;
            case 2: cheb_gemm2_k< 32,  64, 8, 128, true ><<<(n + 63) / 64, 128>>>(W[2], b[2], n, 2); break;
            case 3: cheb_mma_k< 64, 128, true,  false><<<dim3(gx, 2), 256>>>(W[3], b[3], n, 3, nullptr); break;
            case 4: cheb_mma_k<128, 256, false, true ><<<dim3(gx, 4), 256>>>(W[4], b[4], n, 4, bi); break;
        }

        if (l < 4) {
            const int FO = (l == 1) ? 32 : (l == 2) ? 64 : 128;
            int total4 = n * FO / 4;
            int agrid = (total4 + 255) / 256; if (agrid > 2048) agrid = 2048;
            bn_apply_h_k<<<agrid, 256>>>(total4, FO, gm[l], be[l], l, n);
        }
    }

    // ---- dense head (pooling fused into layer-4 mma) ----
    dense_k<<<G, 128>>>(Wd, bd, out);
}